// round 12
// baseline (speedup 1.0000x reference)
#include <cuda_runtime.h>
#include <cuda_bf16.h>
#include <math.h>
#include <stdint.h>

// Problem dims
#define Bz   32
#define Tz   32
#define Nz   256
#define FIN  32
#define FOUT 32
#define Hz   256
#define INz  8192
#define G4   1024
#define GM   1024
#define GK   8192
#define GN   1024

// GEMM tiling
#define BM 128
#define BN 64
#define BK 64
#define NIT (GK / BK)
#define NSTAGE 3
#define OFF_AL 16384
#define OFF_BH 32768
#define OFF_BL 40960
#define STAGE_B 49152
#define SMEM_DYN (NSTAGE * STAGE_B)

// GAT smem layout (dynamic) — conflict-free padded strides
#define HSTR 80
#define ASTR 48
#define GAT_SH_HI   0
#define GAT_SH_LO   20480
#define GAT_AL_HI   40960
#define GAT_AL_LO   65536
#define ABUF        12288
#define GAT_SSRC    90112
#define GAT_SL      91136
#define GAT_SW      92160
#define GAT_SAS     96256
#define GAT_SAD     96384
#define GAT_SBIAS   96512
#define SMEM_GAT    96640

// LSTM cluster config
#define LCL 4
#define LSTM_WSM_F4 (12 * 1024)
#define LSTM_SMEM_DYN (LSTM_WSM_F4 * 16)   // 192 KB

// ---------------------------------------------------------------------------
__device__ __align__(128) __nv_bfloat16 g_seq_hi[(size_t)GM * GK];
__device__ __align__(128) __nv_bfloat16 g_seq_lo[(size_t)GM * GK];
__device__ __align__(128) __nv_bfloat16 g_wih_hi[(size_t)GN * GK];
__device__ __align__(128) __nv_bfloat16 g_wih_lo[(size_t)GN * GK];
__device__ float g_gates[(size_t)GM * G4];
__device__ float4 g_whhT[(Hz / 4) * G4];
__device__ float g_hlast[Bz * Hz];

// ---------------------------------------------------------------------------
__device__ __forceinline__ uint32_t smem_u32(const void* p) {
    return (uint32_t)__cvta_generic_to_shared(p);
}

#define MBARRIER_INIT(addr, cnt) \
    asm volatile("mbarrier.init.shared.b64 [%0], %1;" :: "r"(addr), "r"(cnt) : "memory")
#define MBARRIER_EXPECT_TX(addr, bytes) \
    asm volatile("mbarrier.arrive.expect_tx.shared.b64 _, [%0], %1;" :: "r"(addr), "r"(bytes) : "memory")
#define MBARRIER_WAIT_PARITY(addr, par) do {                                        \
    uint32_t _mbar = (addr); uint32_t _p = (par); uint32_t _done;                   \
    asm volatile("{\n\t.reg .pred p;\n\t"                                           \
        "mbarrier.try_wait.parity.acquire.cta.shared::cta.b64 p, [%1], %2;\n\t"     \
        "selp.b32 %0, 1, 0, p;\n\t}"                                                \
        : "=r"(_done) : "r"(_mbar), "r"(_p) : "memory");                            \
    if (!_done) {                                                                   \
        asm volatile("{\n\t.reg .pred P1;\n\t"                                      \
            "WAIT_LOOP_%=:\n\t"                                                     \
            "mbarrier.try_wait.parity.acquire.cta.shared::cta.b64 P1, [%0], %1, 0x989680;\n\t" \
            "@P1 bra.uni WAIT_DONE_%=;\n\t"                                         \
            "bra.uni WAIT_LOOP_%=;\n\t"                                             \
            "WAIT_DONE_%=:\n\t}"                                                    \
            :: "r"(_mbar), "r"(_p) : "memory");                                     \
    } } while (0)

#define BULK_G2S(dst, src, bytes, mbar) \
    asm volatile("cp.async.bulk.shared::cluster.global.mbarrier::complete_tx::bytes [%0], [%1], %2, [%3];" \
        :: "r"(dst), "l"(src), "r"(bytes), "r"(mbar) : "memory")

#define FENCE_ASYNC() asm volatile("fence.proxy.async.shared::cta;" ::: "memory")

#define CLUSTER_SYNC() do { \
    asm volatile("barrier.cluster.arrive.aligned;" ::: "memory"); \
    asm volatile("barrier.cluster.wait.aligned;" ::: "memory"); \
} while (0)

#define LDSM_X4(r0, r1, r2, r3, addr) \
    asm volatile("ldmatrix.sync.aligned.m8n8.x4.shared.b16 {%0,%1,%2,%3}, [%4];" \
        : "=r"(r0), "=r"(r1), "=r"(r2), "=r"(r3) : "r"(addr))
#define LDSM_X4T(r0, r1, r2, r3, addr) \
    asm volatile("ldmatrix.sync.aligned.m8n8.x4.trans.shared.b16 {%0,%1,%2,%3}, [%4];" \
        : "=r"(r0), "=r"(r1), "=r"(r2), "=r"(r3) : "r"(addr))

__device__ __forceinline__ void mma16816(float* d, const uint32_t* a, const uint32_t* b) {
    asm volatile(
        "mma.sync.aligned.m16n8k16.row.col.f32.bf16.bf16.f32 "
        "{%0,%1,%2,%3}, {%4,%5,%6,%7}, {%8,%9}, {%0,%1,%2,%3};"
        : "+f"(d[0]), "+f"(d[1]), "+f"(d[2]), "+f"(d[3])
        : "r"(a[0]), "r"(a[1]), "r"(a[2]), "r"(a[3]), "r"(b[0]), "r"(b[1]));
}

__device__ __forceinline__ uint32_t pack_bf16x2(float v0, float v1) {
    unsigned short a = __bfloat16_as_ushort(__float2bfloat16(v0));
    unsigned short b = __bfloat16_as_ushort(__float2bfloat16(v1));
    return ((uint32_t)b << 16) | a;
}
__device__ __forceinline__ void split_bf16(float v, float& hi, float& lo) {
    __nv_bfloat16 h = __float2bfloat16(v);
    hi = __bfloat162float(h);
    lo = v - hi;
}

// ---------------------------------------------------------------------------
// Kernel 1: GAT per (b,t). Tensor-core alpha@h, conflict-free padded smem.
// (unchanged from R11)
// ---------------------------------------------------------------------------
__global__ __launch_bounds__(256) void gat_kernel(
    const float* __restrict__ x, const float* __restrict__ adj,
    const float* __restrict__ W, const float* __restrict__ a_src,
    const float* __restrict__ a_dst, const float* __restrict__ gat_b)
{
    extern __shared__ __align__(128) unsigned char gsm[];
    const uint32_t smb = smem_u32(gsm);
    float* ssrc_f  = (float*)(gsm + GAT_SSRC);
    float* sl_f    = (float*)(gsm + GAT_SL);
    float* sW_f    = (float*)(gsm + GAT_SW);
    float* sas_f   = (float*)(gsm + GAT_SAS);
    float* sad_f   = (float*)(gsm + GAT_SAD);
    float* sbias_f = (float*)(gsm + GAT_SBIAS);

    const int bt  = blockIdx.x;
    const int tid = threadIdx.x;
    const int lane = tid & 31;
    const int wid  = tid >> 5;
    const float* xb   = x   + (size_t)bt * Nz * FIN;
    const float* adjb = adj + (size_t)bt * Nz * Nz;

    for (int i = tid; i < FIN * FOUT; i += 256) sW_f[i] = W[i];
    if (tid < FOUT) { sas_f[tid] = a_src[tid]; sad_f[tid] = a_dst[tid]; sbias_f[tid] = gat_b[tid]; }
    __syncthreads();

    float xv[FIN];
#pragma unroll
    for (int k = 0; k < FIN; k++) xv[k] = xb[tid * FIN + k];
    float hv[FOUT];
    float vsrc = 0.f, vdst = 0.f;
#pragma unroll
    for (int o = 0; o < FOUT; o++) {
        float acc = 0.f;
#pragma unroll
        for (int k = 0; k < FIN; k++) acc = fmaf(xv[k], sW_f[k * FOUT + o], acc);
        hv[o] = acc;
        vsrc = fmaf(acc, sas_f[o], vsrc);
        vdst = fmaf(acc, sad_f[o], vdst);
    }
    ssrc_f[tid] = vsrc;
#pragma unroll
    for (int g = 0; g < 4; g++) {
        float h8h[8], h8l[8];
#pragma unroll
        for (int e = 0; e < 8; e++) split_bf16(hv[g*8 + e], h8h[e], h8l[e]);
        uint4 uh = { pack_bf16x2(h8h[0],h8h[1]), pack_bf16x2(h8h[2],h8h[3]),
                     pack_bf16x2(h8h[4],h8h[5]), pack_bf16x2(h8h[6],h8h[7]) };
        uint4 ul = { pack_bf16x2(h8l[0],h8l[1]), pack_bf16x2(h8l[2],h8l[3]),
                     pack_bf16x2(h8l[4],h8l[5]), pack_bf16x2(h8l[6],h8l[7]) };
        *(uint4*)(gsm + GAT_SH_HI + tid * HSTR + g * 16) = uh;
        *(uint4*)(gsm + GAT_SH_LO + tid * HSTR + g * 16) = ul;
    }
    __syncthreads();

    float d[2][4][4];
#pragma unroll
    for (int i = 0; i < 2; i++)
#pragma unroll
        for (int j = 0; j < 4; j++)
#pragma unroll
            for (int q = 0; q < 4; q++) d[i][j][q] = 0.f;
    float l = 0.f;

    const int i0 = wid * 32;
    const uint32_t lrow = (lane & 7) + ((lane >> 3) & 1) * 8;
    const uint32_t lhalf = (lane >> 4) & 1;
    const uint32_t aAddrBase = smb + GAT_AL_HI + (i0 + lrow) * ASTR + lhalf * 16;
    const uint32_t bAddrBase = smb + GAT_SH_HI + lrow * HSTR + lhalf * 16;

    for (int c = 0; c < 16; c++) {
        const int buf = c & 1;
        float av[16];
#pragma unroll
        for (int jj = 0; jj < 16; jj++)
            av[jj] = adjb[(size_t)(c * 16 + jj) * Nz + tid];
        uint32_t phi[8], plo[8];
#pragma unroll
        for (int q = 0; q < 8; q++) {
            float p2[2];
#pragma unroll
            for (int u = 0; u < 2; u++) {
                int jj = q * 2 + u;
                int j  = c * 16 + jj;
                float e = vdst + ssrc_f[j];
                e = (e > 0.f) ? e : 0.2f * e;
                float pe = __expf(e);
                bool edge = (av[jj] != 0.f) | (j == tid);
                p2[u] = edge ? pe : 0.f;
                l += p2[u];
            }
            float h0, l0, h1, l1;
            split_bf16(p2[0], h0, l0);
            split_bf16(p2[1], h1, l1);
            phi[q] = pack_bf16x2(h0, h1);
            plo[q] = pack_bf16x2(l0, l1);
        }
        {
            unsigned char* arow = gsm + buf * ABUF + tid * ASTR;
            *(uint4*)(arow + GAT_AL_HI)      = *(uint4*)&phi[0];
            *(uint4*)(arow + GAT_AL_HI + 16) = *(uint4*)&phi[4];
            *(uint4*)(arow + GAT_AL_LO)      = *(uint4*)&plo[0];
            *(uint4*)(arow + GAT_AL_LO + 16) = *(uint4*)&plo[4];
        }
        __syncthreads();

        uint32_t ah[2][4], al[2][4], bh[2][4], bl[2][4];
        uint32_t aA = aAddrBase + buf * ABUF;
        LDSM_X4(ah[0][0], ah[0][1], ah[0][2], ah[0][3], aA);
        LDSM_X4(ah[1][0], ah[1][1], ah[1][2], ah[1][3], aA + 16 * ASTR);
        LDSM_X4(al[0][0], al[0][1], al[0][2], al[0][3], aA + (GAT_AL_LO - GAT_AL_HI));
        LDSM_X4(al[1][0], al[1][1], al[1][2], al[1][3], aA + (GAT_AL_LO - GAT_AL_HI) + 16 * ASTR);
        uint32_t bA = bAddrBase + c * 16 * HSTR;
        LDSM_X4T(bh[0][0], bh[0][1], bh[0][2], bh[0][3], bA);
        LDSM_X4T(bh[1][0], bh[1][1], bh[1][2], bh[1][3], bA + 32);
        LDSM_X4T(bl[0][0], bl[0][1], bl[0][2], bl[0][3], bA + (GAT_SH_LO - GAT_SH_HI));
        LDSM_X4T(bl[1][0], bl[1][1], bl[1][2], bl[1][3], bA + (GAT_SH_LO - GAT_SH_HI) + 32);
#pragma unroll
        for (int mt = 0; mt < 2; mt++)
#pragma unroll
            for (int ng = 0; ng < 2; ng++)
#pragma unroll
                for (int hf = 0; hf < 2; hf++) {
                    float* dd = d[mt][ng * 2 + hf];
                    mma16816(dd, ah[mt], &bh[ng][hf * 2]);
                    mma16816(dd, ah[mt], &bl[ng][hf * 2]);
                    mma16816(dd, al[mt], &bh[ng][hf * 2]);
                }
    }

    sl_f[tid] = 1.f / l;
    __syncthreads();

    const int mtile = bt >> 7, mrow = bt & 127;
    unsigned char* seqh = (unsigned char*)g_seq_hi + (((size_t)mtile * 128) << 14);
    unsigned char* seql = (unsigned char*)g_seq_lo + (((size_t)mtile * 128) << 14);
#pragma unroll
    for (int mt = 0; mt < 2; mt++) {
        int r0 = i0 + mt * 16 + (lane >> 2);
        int r1 = r0 + 8;
        float inv0 = sl_f[r0], inv1 = sl_f[r1];
#pragma unroll
        for (int nt = 0; nt < 4; nt++) {
            int o = nt * 8 + (lane & 3) * 2;
            float b0 = sbias_f[o], b1 = sbias_f[o + 1];
            float v00 = fmaf(d[mt][nt][0], inv0, b0);
            float v01 = fmaf(d[mt][nt][1], inv0, b1);
            float v10 = fmaf(d[mt][nt][2], inv1, b0);
            float v11 = fmaf(d[mt][nt][3], inv1, b1);
            float h00, l00, h01, l01, h10, l10, h11, l11;
            split_bf16(v00, h00, l00); split_bf16(v01, h01, l01);
            split_bf16(v10, h10, l10); split_bf16(v11, h11, l11);
            {
                int k0 = r0 * 32 + o;
                uint32_t byte = (uint32_t)mrow * 128 + (k0 & 63) * 2;
                uint32_t sw = byte ^ ((byte >> 3) & 0x70);
                size_t off = ((size_t)(k0 >> 6) << 14) + sw;
                *(uint32_t*)(seqh + off) = pack_bf16x2(h00, h01);
                *(uint32_t*)(seql + off) = pack_bf16x2(l00, l01);
            }
            {
                int k1 = r1 * 32 + o;
                uint32_t byte = (uint32_t)mrow * 128 + (k1 & 63) * 2;
                uint32_t sw = byte ^ ((byte >> 3) & 0x70);
                size_t off = ((size_t)(k1 >> 6) << 14) + sw;
                *(uint32_t*)(seqh + off) = pack_bf16x2(h10, h11);
                *(uint32_t*)(seql + off) = pack_bf16x2(l10, l11);
            }
        }
    }
}

// ---------------------------------------------------------------------------
// Kernel 1b: W_ih fp32 -> swizzled tiled bf16 hi/lo (4096 blocks)
// ---------------------------------------------------------------------------
__global__ __launch_bounds__(256) void conv_wih_kernel(const float* __restrict__ W_ih)
{
    size_t t = (size_t)blockIdx.x * 256 + threadIdx.x;
    int n = (int)(t >> 10);
    int s = (int)(t & 1023);
    int k0 = s * 8;
    const float* src = W_ih + (size_t)n * GK + k0;
    float4 v0 = *(const float4*)(src);
    float4 v1 = *(const float4*)(src + 4);
    float f[8] = {v0.x, v0.y, v0.z, v0.w, v1.x, v1.y, v1.z, v1.w};
    float fh[8], fl[8];
#pragma unroll
    for (int i = 0; i < 8; i++) split_bf16(f[i], fh[i], fl[i]);
    int ntile = n >> 7, nrow = n & 127, chunk = s >> 3, seg = s & 7;
    size_t off = (((size_t)(ntile * 128 + chunk)) << 14) + nrow * 128
               + (uint32_t)((seg ^ (nrow & 7)) << 4);
    uint4 uh, ul;
    uh.x = pack_bf16x2(fh[0], fh[1]); uh.y = pack_bf16x2(fh[2], fh[3]);
    uh.z = pack_bf16x2(fh[4], fh[5]); uh.w = pack_bf16x2(fh[6], fh[7]);
    ul.x = pack_bf16x2(fl[0], fl[1]); ul.y = pack_bf16x2(fl[2], fl[3]);
    ul.z = pack_bf16x2(fl[4], fl[5]); ul.w = pack_bf16x2(fl[6], fl[7]);
    *(uint4*)((unsigned char*)g_wih_hi + off) = uh;
    *(uint4*)((unsigned char*)g_wih_lo + off) = ul;
}

// ---------------------------------------------------------------------------
// Kernel 1c: W_hh -> packed transpose (256 blocks)
// ---------------------------------------------------------------------------
__global__ __launch_bounds__(256) void conv_whh_kernel(const float* __restrict__ W_hh)
{
    int t = blockIdx.x * 256 + threadIdx.x;
    int g  = t & 1023;
    int k4 = t >> 10;
    float4 v = *(const float4*)(W_hh + (size_t)g * Hz + k4 * 4);
    g_whhT[k4 * G4 + g] = v;
}

// ---------------------------------------------------------------------------
// Kernel 2: split-bf16 mma.sync GEMM, 512 threads. Warp pairs share a 32x32
// output tile, splitting the 4 k16-segments 2+2 (wk); epilogue reduces pairs.
// ---------------------------------------------------------------------------
__global__ __launch_bounds__(512) void tc_gemm_kernel(
    const float* __restrict__ b_ih, const float* __restrict__ b_hh)
{
    extern __shared__ __align__(128) unsigned char dsmem[];
    __shared__ __align__(8) unsigned long long s_full[NSTAGE];
    const uint32_t dsm = smem_u32(dsmem);

    const int tid  = threadIdx.x;
    const int lane = tid & 31;
    const int wid  = tid >> 5;          // 0..15
    const int tile_w = wid & 7;         // output tile position
    const int wk     = wid >> 3;        // k half: 0 -> ksegs {0,1}, 1 -> {2,3}
    const int warp_m = tile_w >> 1;     // 0..3
    const int warp_n = tile_w & 1;      // 0..1
    const int mblk = blockIdx.y * BM;
    const int nblk = blockIdx.x * BN;
    const int mtile = blockIdx.y;
    const int ntile = blockIdx.x >> 1;
    const size_t bhalf = (size_t)(blockIdx.x & 1) * 8192;

    if (tid == 0) {
        for (int p = 0; p < NSTAGE; p++) MBARRIER_INIT(smem_u32(&s_full[p]), 1);
        FENCE_ASYNC();
    }
    __syncthreads();

    const unsigned char* srcAh = (const unsigned char*)g_seq_hi + (((size_t)mtile * 128) << 14);
    const unsigned char* srcAl = (const unsigned char*)g_seq_lo + (((size_t)mtile * 128) << 14);
    const unsigned char* srcBh = (const unsigned char*)g_wih_hi + (((size_t)ntile * 128) << 14) + bhalf;
    const unsigned char* srcBl = (const unsigned char*)g_wih_lo + (((size_t)ntile * 128) << 14) + bhalf;

    auto issue_stage = [&](int st, int it) {
        uint32_t sb = dsm + st * STAGE_B;
        uint32_t fb = smem_u32(&s_full[st]);
        size_t off = (size_t)it << 14;
        MBARRIER_EXPECT_TX(fb, STAGE_B);
        BULK_G2S(sb,          srcAh + off, 16384, fb);
        BULK_G2S(sb + OFF_AL, srcAl + off, 16384, fb);
        BULK_G2S(sb + OFF_BH, srcBh + off,  8192, fb);
        BULK_G2S(sb + OFF_BL, srcBl + off,  8192, fb);
    };

    if (tid == 0) {
        issue_stage(0, 0);
        issue_stage(1, 1);
        issue_stage(2, 2);
    }

    const int rA  = warp_m * 32 + (lane & 7) + ((lane >> 3) & 1) * 8;
    const int aHf = lane >> 4;
    const int r7a = rA & 7;
    const int rB  = warp_n * 32 + (lane & 7) + ((lane >> 4) & 1) * 8;
    const int bHf = (lane >> 3) & 1;
    const int r7b = rB & 7;
    const uint32_t aoff0 = (uint32_t)rA * 128;
    const uint32_t aoff1 = aoff0 + 16 * 128;
    const uint32_t boff0 = (uint32_t)rB * 128;
    const uint32_t boff1 = boff0 + 16 * 128;

    float d[2][4][4];
#pragma unroll
    for (int i = 0; i < 2; i++)
#pragma unroll
        for (int j = 0; j < 4; j++)
#pragma unroll
            for (int q = 0; q < 4; q++) d[i][j][q] = 0.f;

    const int ks0 = wk * 2;

    for (int it = 0; it < NIT; it++) {
        int s = it % NSTAGE;
        MBARRIER_WAIT_PARITY(smem_u32(&s_full[s]), (it / NSTAGE) & 1);

        uint32_t sA = dsm + s * STAGE_B;
        uint32_t sB = sA + OFF_BH;
#pragma unroll
        for (int kq = 0; kq < 2; kq++) {
            int kseg = (ks0 + kq) * 2;
            uint32_t ah[2][4], al[2][4], bh[2][4], bl[2][4];
            {
                uint32_t asg = (uint32_t)(((kseg + aHf) ^ r7a) << 4);
                uint32_t ad0 = sA + aoff0 + asg;
                uint32_t ad1 = sA + aoff1 + asg;
                LDSM_X4(ah[0][0], ah[0][1], ah[0][2], ah[0][3], ad0);
                LDSM_X4(ah[1][0], ah[1][1], ah[1][2], ah[1][3], ad1);
                LDSM_X4(al[0][0], al[0][1], al[0][2], al[0][3], ad0 + OFF_AL);
                LDSM_X4(al[1][0], al[1][1], al[1][2], al[1][3], ad1 + OFF_AL);
            }
            {
                uint32_t bsg = (uint32_t)(((kseg + bHf) ^ r7b) << 4);
                uint32_t bd0 = sB + boff0 + bsg;
                uint32_t bd1 = sB + boff1 + bsg;
                LDSM_X4(bh[0][0], bh[0][1], bh[0][2], bh[0][3], bd0);
                LDSM_X4(bh[1][0], bh[1][1], bh[1][2], bh[1][3], bd1);
                LDSM_X4(bl[0][0], bl[0][1], bl[0][2], bl[0][3], bd0 + 8192);
                LDSM_X4(bl[1][0], bl[1][1], bl[1][2], bl[1][3], bd1 + 8192);
            }
#pragma unroll
            for (int mt = 0; mt < 2; mt++)
#pragma unroll
                for (int p = 0; p < 2; p++)
#pragma unroll
                    for (int hf = 0; hf < 2; hf++) {
                        float* dd = d[mt][p * 2 + hf];
                        mma16816(dd, ah[mt], &bh[p][hf * 2]);
                        mma16816(dd, ah[mt], &bl[p][hf * 2]);
                        mma16816(dd, al[mt], &bh[p][hf * 2]);
                    }
        }
        __syncthreads();
        if (tid == 0 && it + NSTAGE < NIT) issue_stage(s, it + NSTAGE);
    }

    // ---- cross-warp (wk) reduction through smem; conflict-free layout ----
    float* red = (float*)dsmem;     // 8 tiles * 1024 floats = 32KB (stage reuse)
    float* df = &d[0][0][0];
    if (wk == 1) {
#pragma unroll
        for (int i = 0; i < 8; i++)
            *(float4*)(red + tile_w * 1024 + i * 128 + lane * 4) = ((float4*)df)[i];
    }
    __syncthreads();
    if (wk == 0) {
#pragma unroll
        for (int i = 0; i < 8; i++) {
            float4 v = *(const float4*)(red + tile_w * 1024 + i * 128 + lane * 4);
            df[i*4+0] += v.x; df[i*4+1] += v.y; df[i*4+2] += v.z; df[i*4+3] += v.w;
        }
#pragma unroll
        for (int mt = 0; mt < 2; mt++) {
#pragma unroll
            for (int nt = 0; nt < 4; nt++) {
                int rowm = mblk + warp_m * 32 + mt * 16 + (lane >> 2);
                int coln = nblk + warp_n * 32 + nt * 8 + (lane & 3) * 2;
                float bi0 = b_ih[coln]     + b_hh[coln];
                float bi1 = b_ih[coln + 1] + b_hh[coln + 1];
                float* p0 = g_gates + (size_t)rowm * GN + coln;
                float* p1 = g_gates + (size_t)(rowm + 8) * GN + coln;
                float2 v0 = {d[mt][nt][0] + bi0, d[mt][nt][1] + bi1};
                float2 v1 = {d[mt][nt][2] + bi0, d[mt][nt][3] + bi1};
                *(float2*)p0 = v0;
                *(float2*)p1 = v1;
            }
        }
    }
}

// ---------------------------------------------------------------------------
// Kernel 3: LSTM recurrence — cluster-4 k-split (unchanged from R11)
// ---------------------------------------------------------------------------
__global__ __launch_bounds__(1024, 1) __cluster_dims__(LCL, 1, 1)
void lstm_kernel()
{
    extern __shared__ __align__(16) float4 wsm[];
    __shared__ __align__(16) float hloc[64];
    __shared__ __align__(16) float pbuf[2][LCL * 256];

    const int tid = threadIdx.x;
    uint32_t rank;
    asm("mov.u32 %0, %%cluster_ctarank;" : "=r"(rank));
    const int b = blockIdx.y;
    const int j = tid & 255;
    const int q = tid >> 8;
    const int ro = j >> 6;
    const int slot = (int)rank * 256 + q * 64 + (j & 63);

    uint32_t rem[2];
    {
        uint32_t l0 = smem_u32(&pbuf[0][slot]);
        uint32_t l1 = smem_u32(&pbuf[1][slot]);
        asm("mapa.shared::cluster.u32 %0, %1, %2;" : "=r"(rem[0]) : "r"(l0), "r"(ro));
        asm("mapa.shared::cluster.u32 %0, %1, %2;" : "=r"(rem[1]) : "r"(l1), "r"(ro));
    }

    const float4* wp = g_whhT + (size_t)(rank * 16) * G4 + tid;
#pragma unroll
    for (int i = 0; i < 12; i++) wsm[i * 1024 + tid] = wp[i * G4];

    if (tid < 64) hloc[tid] = 0.f;
    float c = 0.f;
    const float* pre = g_gates + (size_t)b * Tz * G4;
    const int hglob = rank * 64 + tid;

    __syncthreads();

    for (int t = 0; t < Tz; t++) {
        float a0 = 0.f, a1 = 0.f;
        const float4* h4 = (const float4*)hloc;
#pragma unroll
        for (int i = 0; i < 12; i += 2) {
            float4 w0 = wsm[i * 1024 + tid];
            float4 w1 = wsm[(i + 1) * 1024 + tid];
            float4 h0 = h4[i], h1 = h4[i + 1];
            a0 = fmaf(w0.x, h0.x, a0); a0 = fmaf(w0.y, h0.y, a0);
            a0 = fmaf(w0.z, h0.z, a0); a0 = fmaf(w0.w, h0.w, a0);
            a1 = fmaf(w1.x, h1.x, a1); a1 = fmaf(w1.y, h1.y, a1);
            a1 = fmaf(w1.z, h1.z, a1); a1 = fmaf(w1.w, h1.w, a1);
        }
#pragma unroll
        for (int i = 12; i < 16; i += 2) {
            float4 w0 = wp[i * G4];
            float4 w1 = wp[(i + 1) * G4];
            float4 h0 = h4[i], h1 = h4[i + 1];
            a0 = fmaf(w0.x, h0.x, a0); a0 = fmaf(w0.y, h0.y, a0);
            a0 = fmaf(w0.z, h0.z, a0); a0 = fmaf(w0.w, h0.w, a0);
            a1 = fmaf(w1.x, h1.x, a1); a1 = fmaf(w1.y, h1.y, a1);
            a1 = fmaf(w1.z, h1.z, a1); a1 = fmaf(w1.w, h1.w, a1);
        }
        float partial = a0 + a1;

        asm volatile("st.shared::cluster.b32 [%0], %1;"
                     :: "r"(rem[t & 1]), "r"(__float_as_uint(partial)) : "memory");
        CLUSTER_SYNC();

        if (tid < 64) {
            const float* pb = pbuf[t & 1];
            float gs[4];
#pragma unroll
            for (int qq = 0; qq < 4; qq++) {
                float s = pre[t * G4 + qq * 256 + hglob];
#pragma unroll
                for (int src = 0; src < LCL; src++)
                    s += pb[src * 256 + qq * 64 + tid];
                gs[qq] = s;
            }
            float gi = 1.f / (1.f + __expf(-gs[0]));
            float gf = 1.f / (1.f + __expf(-gs[1]));
            float gg = tanhf(gs[2]);
            float go = 1.f / (1.f + __expf(-gs[3]));
            c = gf * c + gi * gg;
            hloc[tid] = go * tanhf(c);
        }
        __syncthreads();
    }

    if (tid < 64) g_hlast[b * Hz + hglob] = hloc[tid];
    CLUSTER_SYNC();
}

// ---------------------------------------------------------------------------
// Kernel 4: output linear
// ---------------------------------------------------------------------------
__global__ __launch_bounds__(256) void out_kernel(
    const float* __restrict__ Wo, const float* __restrict__ bo,
    float* __restrict__ out)
{
    const int b = blockIdx.x, n = threadIdx.x;
    const float4* h4 = (const float4*)(g_hlast + b * Hz);
    const float4* w4 = (const float4*)(Wo + n * Hz);
    float acc = bo[n];
#pragma unroll 8
    for (int k = 0; k < Hz / 4; k++) {
        float4 w = w4[k], h = h4[k];
        acc = fmaf(w.x, h.x, acc);
        acc = fmaf(w.y, h.y, acc);
        acc = fmaf(w.z, h.z, acc);
        acc = fmaf(w.w, h.w, acc);
    }
    out[b * Nz + n] = acc;
}

// ---------------------------------------------------------------------------
extern "C" void kernel_launch(void* const* d_in, const int* in_sizes, int n_in,
                              void* d_out, int out_size)
{
    const float* x     = (const float*)d_in[0];
    const float* adj   = (const float*)d_in[1];
    const float* W     = (const float*)d_in[2];
    const float* a_src = (const float*)d_in[3];
    const float* a_dst = (const float*)d_in[4];
    const float* gat_b = (const float*)d_in[5];
    const float* W_ih  = (const float*)d_in[6];
    const float* W_hh  = (const float*)d_in[7];
    const float* b_ih  = (const float*)d_in[8];
    const float* b_hh  = (const float*)d_in[9];
    const float* Wo    = (const float*)d_in[10];
    const float* bo    = (const float*)d_in[11];
    float* out = (float*)d_out;

    cudaFuncSetAttribute(tc_gemm_kernel,
                         cudaFuncAttributeMaxDynamicSharedMemorySize, SMEM_DYN);
    cudaFuncSetAttribute(gat_kernel,
                         cudaFuncAttributeMaxDynamicSharedMemorySize, SMEM_GAT);
    cudaFuncSetAttribute(lstm_kernel,
                         cudaFuncAttributeMaxDynamicSharedMemorySize, LSTM_SMEM_DYN);

    // index 3 (0-based) = ncu profiled slot -> tc_gemm this round
    conv_wih_kernel<<<4096, 256>>>(W_ih);                                 // 0
    conv_whh_kernel<<<256, 256>>>(W_hh);                                  // 1
    gat_kernel<<<GM, 256, SMEM_GAT>>>(x, adj, W, a_src, a_dst, gat_b);    // 2

    dim3 gg(GN / BN, GM / BM);
    tc_gemm_kernel<<<gg, 512, SMEM_DYN>>>(b_ih, b_hh);                    // 3 (profiled)

    lstm_kernel<<<dim3(LCL, Bz), 1024, LSTM_SMEM_DYN>>>();                // 4
    out_kernel<<<Bz, 256>>>(Wo, bo, out);                                 // 5
}

// round 13
// speedup vs baseline: 1.1088x; 1.1088x over previous
#include <cuda_runtime.h>
#include <cuda_bf16.h>
#include <cuda_fp16.h>
#include <math.h>
#include <stdint.h>

// Problem dims
#define Bz   32
#define Tz   32
#define Nz   256
#define FIN  32
#define FOUT 32
#define Hz   256
#define INz  8192
#define G4   1024
#define GM   1024
#define GK   8192
#define GN   1024

// GEMM tiling (fp16 2-pass: A hi only, B hi+lo)
#define BM 128
#define BN 64
#define BK 64
#define NIT (GK / BK)
#define NSTAGE 4
#define OFF_BH 16384
#define OFF_BL 24576
#define STAGE_B 32768
#define SMEM_DYN (NSTAGE * STAGE_B)   // 128 KB

// GAT smem layout (dynamic) — conflict-free padded strides
#define HSTR 80
#define ASTR 48
#define GAT_SH_HI   0
#define GAT_SH_LO   20480
#define GAT_AL_HI   40960
#define GAT_AL_LO   65536
#define ABUF        12288
#define GAT_SSRC    90112
#define GAT_SL      91136
#define GAT_SW      92160
#define GAT_SAS     96256
#define GAT_SAD     96384
#define GAT_SBIAS   96512
#define SMEM_GAT    96640

// LSTM cluster config
#define LCL 4
#define LSTM_WSM_F4 (12 * 1024)
#define LSTM_SMEM_DYN (LSTM_WSM_F4 * 16)   // 192 KB

// ---------------------------------------------------------------------------
// seq: fp16 (single copy); wih: fp16 hi/lo. Swizzled tiled layout:
// offset = ((rowtile*128 + kchunk) << 14) + row*128 + ((seg^(row&7))<<4) + (k&7)*2
// ---------------------------------------------------------------------------
__device__ __align__(128) __half g_seq[(size_t)GM * GK];
__device__ __align__(128) __half g_wih_hi[(size_t)GN * GK];
__device__ __align__(128) __half g_wih_lo[(size_t)GN * GK];
__device__ float g_gates[(size_t)GM * G4];
__device__ float4 g_whhT[(Hz / 4) * G4];
__device__ float g_hlast[Bz * Hz];

// ---------------------------------------------------------------------------
__device__ __forceinline__ uint32_t smem_u32(const void* p) {
    return (uint32_t)__cvta_generic_to_shared(p);
}

#define MBARRIER_INIT(addr, cnt) \
    asm volatile("mbarrier.init.shared.b64 [%0], %1;" :: "r"(addr), "r"(cnt) : "memory")
#define MBARRIER_EXPECT_TX(addr, bytes) \
    asm volatile("mbarrier.arrive.expect_tx.shared.b64 _, [%0], %1;" :: "r"(addr), "r"(bytes) : "memory")
#define MBARRIER_WAIT_PARITY(addr, par) do {                                        \
    uint32_t _mbar = (addr); uint32_t _p = (par); uint32_t _done;                   \
    asm volatile("{\n\t.reg .pred p;\n\t"                                           \
        "mbarrier.try_wait.parity.acquire.cta.shared::cta.b64 p, [%1], %2;\n\t"     \
        "selp.b32 %0, 1, 0, p;\n\t}"                                                \
        : "=r"(_done) : "r"(_mbar), "r"(_p) : "memory");                            \
    if (!_done) {                                                                   \
        asm volatile("{\n\t.reg .pred P1;\n\t"                                      \
            "WAIT_LOOP_%=:\n\t"                                                     \
            "mbarrier.try_wait.parity.acquire.cta.shared::cta.b64 P1, [%0], %1, 0x989680;\n\t" \
            "@P1 bra.uni WAIT_DONE_%=;\n\t"                                         \
            "bra.uni WAIT_LOOP_%=;\n\t"                                             \
            "WAIT_DONE_%=:\n\t}"                                                    \
            :: "r"(_mbar), "r"(_p) : "memory");                                     \
    } } while (0)

#define BULK_G2S(dst, src, bytes, mbar) \
    asm volatile("cp.async.bulk.shared::cluster.global.mbarrier::complete_tx::bytes [%0], [%1], %2, [%3];" \
        :: "r"(dst), "l"(src), "r"(bytes), "r"(mbar) : "memory")

#define FENCE_ASYNC() asm volatile("fence.proxy.async.shared::cta;" ::: "memory")

#define CLUSTER_SYNC() do { \
    asm volatile("barrier.cluster.arrive.aligned;" ::: "memory"); \
    asm volatile("barrier.cluster.wait.aligned;" ::: "memory"); \
} while (0)

#define LDSM_X4(r0, r1, r2, r3, addr) \
    asm volatile("ldmatrix.sync.aligned.m8n8.x4.shared.b16 {%0,%1,%2,%3}, [%4];" \
        : "=r"(r0), "=r"(r1), "=r"(r2), "=r"(r3) : "r"(addr))
#define LDSM_X4T(r0, r1, r2, r3, addr) \
    asm volatile("ldmatrix.sync.aligned.m8n8.x4.trans.shared.b16 {%0,%1,%2,%3}, [%4];" \
        : "=r"(r0), "=r"(r1), "=r"(r2), "=r"(r3) : "r"(addr))

// bf16 mma (GAT path)
__device__ __forceinline__ void mma16816(float* d, const uint32_t* a, const uint32_t* b) {
    asm volatile(
        "mma.sync.aligned.m16n8k16.row.col.f32.bf16.bf16.f32 "
        "{%0,%1,%2,%3}, {%4,%5,%6,%7}, {%8,%9}, {%0,%1,%2,%3};"
        : "+f"(d[0]), "+f"(d[1]), "+f"(d[2]), "+f"(d[3])
        : "r"(a[0]), "r"(a[1]), "r"(a[2]), "r"(a[3]), "r"(b[0]), "r"(b[1]));
}
// fp16 mma (big GEMM path)
__device__ __forceinline__ void mma16816h(float* d, const uint32_t* a, const uint32_t* b) {
    asm volatile(
        "mma.sync.aligned.m16n8k16.row.col.f32.f16.f16.f32 "
        "{%0,%1,%2,%3}, {%4,%5,%6,%7}, {%8,%9}, {%0,%1,%2,%3};"
        : "+f"(d[0]), "+f"(d[1]), "+f"(d[2]), "+f"(d[3])
        : "r"(a[0]), "r"(a[1]), "r"(a[2]), "r"(a[3]), "r"(b[0]), "r"(b[1]));
}

__device__ __forceinline__ uint32_t pack_bf16x2(float v0, float v1) {
    unsigned short a = __bfloat16_as_ushort(__float2bfloat16(v0));
    unsigned short b = __bfloat16_as_ushort(__float2bfloat16(v1));
    return ((uint32_t)b << 16) | a;
}
__device__ __forceinline__ void split_bf16(float v, float& hi, float& lo) {
    __nv_bfloat16 h = __float2bfloat16(v);
    hi = __bfloat162float(h);
    lo = v - hi;
}
__device__ __forceinline__ uint32_t pack_f16x2(float v0, float v1) {
    __half2 h = __floats2half2_rn(v0, v1);
    return *(uint32_t*)&h;
}
__device__ __forceinline__ void split_f16(float v, float& hi, float& lo) {
    __half h = __float2half_rn(v);
    hi = __half2float(h);
    lo = v - hi;
}

// ---------------------------------------------------------------------------
// Kernel 1: GAT per (b,t). Tensor-core alpha@h (bf16 3-pass), padded smem.
// Epilogue writes seq as plain fp16 into swizzled tiled layout.
// ---------------------------------------------------------------------------
__global__ __launch_bounds__(256) void gat_kernel(
    const float* __restrict__ x, const float* __restrict__ adj,
    const float* __restrict__ W, const float* __restrict__ a_src,
    const float* __restrict__ a_dst, const float* __restrict__ gat_b)
{
    extern __shared__ __align__(128) unsigned char gsm[];
    const uint32_t smb = smem_u32(gsm);
    float* ssrc_f  = (float*)(gsm + GAT_SSRC);
    float* sl_f    = (float*)(gsm + GAT_SL);
    float* sW_f    = (float*)(gsm + GAT_SW);
    float* sas_f   = (float*)(gsm + GAT_SAS);
    float* sad_f   = (float*)(gsm + GAT_SAD);
    float* sbias_f = (float*)(gsm + GAT_SBIAS);

    const int bt  = blockIdx.x;
    const int tid = threadIdx.x;
    const int lane = tid & 31;
    const int wid  = tid >> 5;
    const float* xb   = x   + (size_t)bt * Nz * FIN;
    const float* adjb = adj + (size_t)bt * Nz * Nz;

    for (int i = tid; i < FIN * FOUT; i += 256) sW_f[i] = W[i];
    if (tid < FOUT) { sas_f[tid] = a_src[tid]; sad_f[tid] = a_dst[tid]; sbias_f[tid] = gat_b[tid]; }
    __syncthreads();

    float xv[FIN];
#pragma unroll
    for (int k = 0; k < FIN; k++) xv[k] = xb[tid * FIN + k];
    float hv[FOUT];
    float vsrc = 0.f, vdst = 0.f;
#pragma unroll
    for (int o = 0; o < FOUT; o++) {
        float acc = 0.f;
#pragma unroll
        for (int k = 0; k < FIN; k++) acc = fmaf(xv[k], sW_f[k * FOUT + o], acc);
        hv[o] = acc;
        vsrc = fmaf(acc, sas_f[o], vsrc);
        vdst = fmaf(acc, sad_f[o], vdst);
    }
    ssrc_f[tid] = vsrc;
#pragma unroll
    for (int g = 0; g < 4; g++) {
        float h8h[8], h8l[8];
#pragma unroll
        for (int e = 0; e < 8; e++) split_bf16(hv[g*8 + e], h8h[e], h8l[e]);
        uint4 uh = { pack_bf16x2(h8h[0],h8h[1]), pack_bf16x2(h8h[2],h8h[3]),
                     pack_bf16x2(h8h[4],h8h[5]), pack_bf16x2(h8h[6],h8h[7]) };
        uint4 ul = { pack_bf16x2(h8l[0],h8l[1]), pack_bf16x2(h8l[2],h8l[3]),
                     pack_bf16x2(h8l[4],h8l[5]), pack_bf16x2(h8l[6],h8l[7]) };
        *(uint4*)(gsm + GAT_SH_HI + tid * HSTR + g * 16) = uh;
        *(uint4*)(gsm + GAT_SH_LO + tid * HSTR + g * 16) = ul;
    }
    __syncthreads();

    float d[2][4][4];
#pragma unroll
    for (int i = 0; i < 2; i++)
#pragma unroll
        for (int j = 0; j < 4; j++)
#pragma unroll
            for (int q = 0; q < 4; q++) d[i][j][q] = 0.f;
    float l = 0.f;

    const int i0 = wid * 32;
    const uint32_t lrow = (lane & 7) + ((lane >> 3) & 1) * 8;
    const uint32_t lhalf = (lane >> 4) & 1;
    const uint32_t aAddrBase = smb + GAT_AL_HI + (i0 + lrow) * ASTR + lhalf * 16;
    const uint32_t bAddrBase = smb + GAT_SH_HI + lrow * HSTR + lhalf * 16;

    for (int c = 0; c < 16; c++) {
        const int buf = c & 1;
        float av[16];
#pragma unroll
        for (int jj = 0; jj < 16; jj++)
            av[jj] = adjb[(size_t)(c * 16 + jj) * Nz + tid];
        uint32_t phi[8], plo[8];
#pragma unroll
        for (int q = 0; q < 8; q++) {
            float p2[2];
#pragma unroll
            for (int u = 0; u < 2; u++) {
                int jj = q * 2 + u;
                int j  = c * 16 + jj;
                float e = vdst + ssrc_f[j];
                e = (e > 0.f) ? e : 0.2f * e;
                float pe = __expf(e);
                bool edge = (av[jj] != 0.f) | (j == tid);
                p2[u] = edge ? pe : 0.f;
                l += p2[u];
            }
            float h0, l0, h1, l1;
            split_bf16(p2[0], h0, l0);
            split_bf16(p2[1], h1, l1);
            phi[q] = pack_bf16x2(h0, h1);
            plo[q] = pack_bf16x2(l0, l1);
        }
        {
            unsigned char* arow = gsm + buf * ABUF + tid * ASTR;
            *(uint4*)(arow + GAT_AL_HI)      = *(uint4*)&phi[0];
            *(uint4*)(arow + GAT_AL_HI + 16) = *(uint4*)&phi[4];
            *(uint4*)(arow + GAT_AL_LO)      = *(uint4*)&plo[0];
            *(uint4*)(arow + GAT_AL_LO + 16) = *(uint4*)&plo[4];
        }
        __syncthreads();

        uint32_t ah[2][4], al[2][4], bh[2][4], bl[2][4];
        uint32_t aA = aAddrBase + buf * ABUF;
        LDSM_X4(ah[0][0], ah[0][1], ah[0][2], ah[0][3], aA);
        LDSM_X4(ah[1][0], ah[1][1], ah[1][2], ah[1][3], aA + 16 * ASTR);
        LDSM_X4(al[0][0], al[0][1], al[0][2], al[0][3], aA + (GAT_AL_LO - GAT_AL_HI));
        LDSM_X4(al[1][0], al[1][1], al[1][2], al[1][3], aA + (GAT_AL_LO - GAT_AL_HI) + 16 * ASTR);
        uint32_t bA = bAddrBase + c * 16 * HSTR;
        LDSM_X4T(bh[0][0], bh[0][1], bh[0][2], bh[0][3], bA);
        LDSM_X4T(bh[1][0], bh[1][1], bh[1][2], bh[1][3], bA + 32);
        LDSM_X4T(bl[0][0], bl[0][1], bl[0][2], bl[0][3], bA + (GAT_SH_LO - GAT_SH_HI));
        LDSM_X4T(bl[1][0], bl[1][1], bl[1][2], bl[1][3], bA + (GAT_SH_LO - GAT_SH_HI) + 32);
#pragma unroll
        for (int mt = 0; mt < 2; mt++)
#pragma unroll
            for (int ng = 0; ng < 2; ng++)
#pragma unroll
                for (int hf = 0; hf < 2; hf++) {
                    float* dd = d[mt][ng * 2 + hf];
                    mma16816(dd, ah[mt], &bh[ng][hf * 2]);
                    mma16816(dd, ah[mt], &bl[ng][hf * 2]);
                    mma16816(dd, al[mt], &bh[ng][hf * 2]);
                }
    }

    sl_f[tid] = 1.f / l;
    __syncthreads();

    // ---- epilogue: scale, bias, write fp16 seq (swizzled tiled) ----
    const int mtile = bt >> 7, mrow = bt & 127;
    unsigned char* seqp = (unsigned char*)g_seq + (((size_t)mtile * 128) << 14);
#pragma unroll
    for (int mt = 0; mt < 2; mt++) {
        int r0 = i0 + mt * 16 + (lane >> 2);
        int r1 = r0 + 8;
        float inv0 = sl_f[r0], inv1 = sl_f[r1];
#pragma unroll
        for (int nt = 0; nt < 4; nt++) {
            int o = nt * 8 + (lane & 3) * 2;
            float b0 = sbias_f[o], b1 = sbias_f[o + 1];
            float v00 = fmaf(d[mt][nt][0], inv0, b0);
            float v01 = fmaf(d[mt][nt][1], inv0, b1);
            float v10 = fmaf(d[mt][nt][2], inv1, b0);
            float v11 = fmaf(d[mt][nt][3], inv1, b1);
            {
                int k0 = r0 * 32 + o;
                uint32_t byte = (uint32_t)mrow * 128 + (k0 & 63) * 2;
                uint32_t sw = byte ^ ((byte >> 3) & 0x70);
                size_t off = ((size_t)(k0 >> 6) << 14) + sw;
                *(uint32_t*)(seqp + off) = pack_f16x2(v00, v01);
            }
            {
                int k1 = r1 * 32 + o;
                uint32_t byte = (uint32_t)mrow * 128 + (k1 & 63) * 2;
                uint32_t sw = byte ^ ((byte >> 3) & 0x70);
                size_t off = ((size_t)(k1 >> 6) << 14) + sw;
                *(uint32_t*)(seqp + off) = pack_f16x2(v10, v11);
            }
        }
    }
}

// ---------------------------------------------------------------------------
// Kernel 1b: W_ih fp32 -> swizzled tiled fp16 hi/lo (4096 blocks)
// ---------------------------------------------------------------------------
__global__ __launch_bounds__(256) void conv_wih_kernel(const float* __restrict__ W_ih)
{
    size_t t = (size_t)blockIdx.x * 256 + threadIdx.x;
    int n = (int)(t >> 10);
    int s = (int)(t & 1023);
    int k0 = s * 8;
    const float* src = W_ih + (size_t)n * GK + k0;
    float4 v0 = *(const float4*)(src);
    float4 v1 = *(const float4*)(src + 4);
    float f[8] = {v0.x, v0.y, v0.z, v0.w, v1.x, v1.y, v1.z, v1.w};
    float fh[8], fl[8];
#pragma unroll
    for (int i = 0; i < 8; i++) split_f16(f[i], fh[i], fl[i]);
    int ntile = n >> 7, nrow = n & 127, chunk = s >> 3, seg = s & 7;
    size_t off = (((size_t)(ntile * 128 + chunk)) << 14) + nrow * 128
               + (uint32_t)((seg ^ (nrow & 7)) << 4);
    uint4 uh, ul;
    uh.x = pack_f16x2(fh[0], fh[1]); uh.y = pack_f16x2(fh[2], fh[3]);
    uh.z = pack_f16x2(fh[4], fh[5]); uh.w = pack_f16x2(fh[6], fh[7]);
    ul.x = pack_f16x2(fl[0], fl[1]); ul.y = pack_f16x2(fl[2], fl[3]);
    ul.z = pack_f16x2(fl[4], fl[5]); ul.w = pack_f16x2(fl[6], fl[7]);
    *(uint4*)((unsigned char*)g_wih_hi + off) = uh;
    *(uint4*)((unsigned char*)g_wih_lo + off) = ul;
}

// ---------------------------------------------------------------------------
// Kernel 1c: W_hh -> packed transpose (256 blocks)
// ---------------------------------------------------------------------------
__global__ __launch_bounds__(256) void conv_whh_kernel(const float* __restrict__ W_hh)
{
    int t = blockIdx.x * 256 + threadIdx.x;
    int g  = t & 1023;
    int k4 = t >> 10;
    float4 v = *(const float4*)(W_hh + (size_t)g * Hz + k4 * 4);
    g_whhT[k4 * G4 + g] = v;
}

// ---------------------------------------------------------------------------
// Kernel 2: fp16 2-pass GEMM: D = Ah·Bh + Ah·Bl. 256 threads, 4 stages.
// ---------------------------------------------------------------------------
__global__ __launch_bounds__(256) void tc_gemm_kernel(
    const float* __restrict__ b_ih, const float* __restrict__ b_hh)
{
    extern __shared__ __align__(128) unsigned char dsmem[];
    __shared__ __align__(8) unsigned long long s_full[NSTAGE];
    const uint32_t dsm = smem_u32(dsmem);

    const int tid  = threadIdx.x;
    const int lane = tid & 31;
    const int wid  = tid >> 5;
    const int warp_m = wid >> 1;
    const int warp_n = wid & 1;
    const int mblk = blockIdx.y * BM;
    const int nblk = blockIdx.x * BN;
    const int mtile = blockIdx.y;
    const int ntile = blockIdx.x >> 1;
    const size_t bhalf = (size_t)(blockIdx.x & 1) * 8192;

    if (tid == 0) {
        for (int p = 0; p < NSTAGE; p++) MBARRIER_INIT(smem_u32(&s_full[p]), 1);
        FENCE_ASYNC();
    }
    __syncthreads();

    const unsigned char* srcA  = (const unsigned char*)g_seq    + (((size_t)mtile * 128) << 14);
    const unsigned char* srcBh = (const unsigned char*)g_wih_hi + (((size_t)ntile * 128) << 14) + bhalf;
    const unsigned char* srcBl = (const unsigned char*)g_wih_lo + (((size_t)ntile * 128) << 14) + bhalf;

    auto issue_stage = [&](int st, int it) {
        uint32_t sb = dsm + st * STAGE_B;
        uint32_t fb = smem_u32(&s_full[st]);
        size_t off = (size_t)it << 14;
        MBARRIER_EXPECT_TX(fb, STAGE_B);
        BULK_G2S(sb,          srcA  + off, 16384, fb);
        BULK_G2S(sb + OFF_BH, srcBh + off,  8192, fb);
        BULK_G2S(sb + OFF_BL, srcBl + off,  8192, fb);
    };

    if (tid == 0) {
        issue_stage(0, 0);
        issue_stage(1, 1);
        issue_stage(2, 2);
        issue_stage(3, 3);
    }

    const int rA  = warp_m * 32 + (lane & 7) + ((lane >> 3) & 1) * 8;
    const int aHf = lane >> 4;
    const int r7a = rA & 7;
    const int rB  = warp_n * 32 + (lane & 7) + ((lane >> 4) & 1) * 8;
    const int bHf = (lane >> 3) & 1;
    const int r7b = rB & 7;
    const uint32_t aoff0 = (uint32_t)rA * 128;
    const uint32_t aoff1 = aoff0 + 16 * 128;
    const uint32_t boff0 = (uint32_t)rB * 128;
    const uint32_t boff1 = boff0 + 16 * 128;

    float d[2][4][4];
#pragma unroll
    for (int i = 0; i < 2; i++)
#pragma unroll
        for (int j = 0; j < 4; j++)
#pragma unroll
            for (int q = 0; q < 4; q++) d[i][j][q] = 0.f;

    for (int it = 0; it < NIT; it++) {
        int s = it % NSTAGE;
        MBARRIER_WAIT_PARITY(smem_u32(&s_full[s]), (it / NSTAGE) & 1);

        uint32_t sA = dsm + s * STAGE_B;
        uint32_t sB = sA + OFF_BH;
#pragma unroll
        for (int ks = 0; ks < 4; ks++) {
            int kseg = ks * 2;
            uint32_t a[2][4], bh[2][4], bl[2][4];
            {
                uint32_t asg = (uint32_t)(((kseg + aHf) ^ r7a) << 4);
                uint32_t ad0 = sA + aoff0 + asg;
                uint32_t ad1 = sA + aoff1 + asg;
                LDSM_X4(a[0][0], a[0][1], a[0][2], a[0][3], ad0);
                LDSM_X4(a[1][0], a[1][1], a[1][2], a[1][3], ad1);
            }
            {
                uint32_t bsg = (uint32_t)(((kseg + bHf) ^ r7b) << 4);
                uint32_t bd0 = sB + boff0 + bsg;
                uint32_t bd1 = sB + boff1 + bsg;
                LDSM_X4(bh[0][0], bh[0][1], bh[0][2], bh[0][3], bd0);
                LDSM_X4(bh[1][0], bh[1][1], bh[1][2], bh[1][3], bd1);
                LDSM_X4(bl[0][0], bl[0][1], bl[0][2], bl[0][3], bd0 + 8192);
                LDSM_X4(bl[1][0], bl[1][1], bl[1][2], bl[1][3], bd1 + 8192);
            }
#pragma unroll
            for (int mt = 0; mt < 2; mt++)
#pragma unroll
                for (int p = 0; p < 2; p++)
#pragma unroll
                    for (int hf = 0; hf < 2; hf++) {
                        float* dd = d[mt][p * 2 + hf];
                        mma16816h(dd, a[mt], &bh[p][hf * 2]);
                        mma16816h(dd, a[mt], &bl[p][hf * 2]);
                    }
        }
        __syncthreads();
        if (tid == 0 && it + NSTAGE < NIT) issue_stage(s, it + NSTAGE);
    }

#pragma unroll
    for (int mt = 0; mt < 2; mt++) {
#pragma unroll
        for (int nt = 0; nt < 4; nt++) {
            int rowm = mblk + warp_m * 32 + mt * 16 + (lane >> 2);
            int coln = nblk + warp_n * 32 + nt * 8 + (lane & 3) * 2;
            float bi0 = b_ih[coln]     + b_hh[coln];
            float bi1 = b_ih[coln + 1] + b_hh[coln + 1];
            float* p0 = g_gates + (size_t)rowm * GN + coln;
            float* p1 = g_gates + (size_t)(rowm + 8) * GN + coln;
            float2 v0 = {d[mt][nt][0] + bi0, d[mt][nt][1] + bi1};
            float2 v1 = {d[mt][nt][2] + bi0, d[mt][nt][3] + bi1};
            *(float2*)p0 = v0;
            *(float2*)p1 = v1;
        }
    }
}

// ---------------------------------------------------------------------------
// Kernel 3: LSTM recurrence — cluster-4 k-split (unchanged)
// ---------------------------------------------------------------------------
__global__ __launch_bounds__(1024, 1) __cluster_dims__(LCL, 1, 1)
void lstm_kernel()
{
    extern __shared__ __align__(16) float4 wsm[];
    __shared__ __align__(16) float hloc[64];
    __shared__ __align__(16) float pbuf[2][LCL * 256];

    const int tid = threadIdx.x;
    uint32_t rank;
    asm("mov.u32 %0, %%cluster_ctarank;" : "=r"(rank));
    const int b = blockIdx.y;
    const int j = tid & 255;
    const int q = tid >> 8;
    const int ro = j >> 6;
    const int slot = (int)rank * 256 + q * 64 + (j & 63);

    uint32_t rem[2];
    {
        uint32_t l0 = smem_u32(&pbuf[0][slot]);
        uint32_t l1 = smem_u32(&pbuf[1][slot]);
        asm("mapa.shared::cluster.u32 %0, %1, %2;" : "=r"(rem[0]) : "r"(l0), "r"(ro));
        asm("mapa.shared::cluster.u32 %0, %1, %2;" : "=r"(rem[1]) : "r"(l1), "r"(ro));
    }

    const float4* wp = g_whhT + (size_t)(rank * 16) * G4 + tid;
#pragma unroll
    for (int i = 0; i < 12; i++) wsm[i * 1024 + tid] = wp[i * G4];

    if (tid < 64) hloc[tid] = 0.f;
    float c = 0.f;
    const float* pre = g_gates + (size_t)b * Tz * G4;
    const int hglob = rank * 64 + tid;

    __syncthreads();

    for (int t = 0; t < Tz; t++) {
        float a0 = 0.f, a1 = 0.f;
        const float4* h4 = (const float4*)hloc;
#pragma unroll
        for (int i = 0; i < 12; i += 2) {
            float4 w0 = wsm[i * 1024 + tid];
            float4 w1 = wsm[(i + 1) * 1024 + tid];
            float4 h0 = h4[i], h1 = h4[i + 1];
            a0 = fmaf(w0.x, h0.x, a0); a0 = fmaf(w0.y, h0.y, a0);
            a0 = fmaf(w0.z, h0.z, a0); a0 = fmaf(w0.w, h0.w, a0);
            a1 = fmaf(w1.x, h1.x, a1); a1 = fmaf(w1.y, h1.y, a1);
            a1 = fmaf(w1.z, h1.z, a1); a1 = fmaf(w1.w, h1.w, a1);
        }
#pragma unroll
        for (int i = 12; i < 16; i += 2) {
            float4 w0 = wp[i * G4];
            float4 w1 = wp[(i + 1) * G4];
            float4 h0 = h4[i], h1 = h4[i + 1];
            a0 = fmaf(w0.x, h0.x, a0); a0 = fmaf(w0.y, h0.y, a0);
            a0 = fmaf(w0.z, h0.z, a0); a0 = fmaf(w0.w, h0.w, a0);
            a1 = fmaf(w1.x, h1.x, a1); a1 = fmaf(w1.y, h1.y, a1);
            a1 = fmaf(w1.z, h1.z, a1); a1 = fmaf(w1.w, h1.w, a1);
        }
        float partial = a0 + a1;

        asm volatile("st.shared::cluster.b32 [%0], %1;"
                     :: "r"(rem[t & 1]), "r"(__float_as_uint(partial)) : "memory");
        CLUSTER_SYNC();

        if (tid < 64) {
            const float* pb = pbuf[t & 1];
            float gs[4];
#pragma unroll
            for (int qq = 0; qq < 4; qq++) {
                float s = pre[t * G4 + qq * 256 + hglob];
#pragma unroll
                for (int src = 0; src < LCL; src++)
                    s += pb[src * 256 + qq * 64 + tid];
                gs[qq] = s;
            }
            float gi = 1.f / (1.f + __expf(-gs[0]));
            float gf = 1.f / (1.f + __expf(-gs[1]));
            float gg = tanhf(gs[2]);
            float go = 1.f / (1.f + __expf(-gs[3]));
            c = gf * c + gi * gg;
            hloc[tid] = go * tanhf(c);
        }
        __syncthreads();
    }

    if (tid < 64) g_hlast[b * Hz + hglob] = hloc[tid];
    CLUSTER_SYNC();
}

// ---------------------------------------------------------------------------
// Kernel 4: output linear
// ---------------------------------------------------------------------------
__global__ __launch_bounds__(256) void out_kernel(
    const float* __restrict__ Wo, const float* __restrict__ bo,
    float* __restrict__ out)
{
    const int b = blockIdx.x, n = threadIdx.x;
    const float4* h4 = (const float4*)(g_hlast + b * Hz);
    const float4* w4 = (const float4*)(Wo + n * Hz);
    float acc = bo[n];
#pragma unroll 8
    for (int k = 0; k < Hz / 4; k++) {
        float4 w = w4[k], h = h4[k];
        acc = fmaf(w.x, h.x, acc);
        acc = fmaf(w.y, h.y, acc);
        acc = fmaf(w.z, h.z, acc);
        acc = fmaf(w.w, h.w, acc);
    }
    out[b * Nz + n] = acc;
}

// ---------------------------------------------------------------------------
extern "C" void kernel_launch(void* const* d_in, const int* in_sizes, int n_in,
                              void* d_out, int out_size)
{
    const float* x     = (const float*)d_in[0];
    const float* adj   = (const float*)d_in[1];
    const float* W     = (const float*)d_in[2];
    const float* a_src = (const float*)d_in[3];
    const float* a_dst = (const float*)d_in[4];
    const float* gat_b = (const float*)d_in[5];
    const float* W_ih  = (const float*)d_in[6];
    const float* W_hh  = (const float*)d_in[7];
    const float* b_ih  = (const float*)d_in[8];
    const float* b_hh  = (const float*)d_in[9];
    const float* Wo    = (const float*)d_in[10];
    const float* bo    = (const float*)d_in[11];
    float* out = (float*)d_out;

    cudaFuncSetAttribute(tc_gemm_kernel,
                         cudaFuncAttributeMaxDynamicSharedMemorySize, SMEM_DYN);
    cudaFuncSetAttribute(gat_kernel,
                         cudaFuncAttributeMaxDynamicSharedMemorySize, SMEM_GAT);
    cudaFuncSetAttribute(lstm_kernel,
                         cudaFuncAttributeMaxDynamicSharedMemorySize, LSTM_SMEM_DYN);

    // index 3 (0-based) = ncu profiled slot -> tc_gemm
    conv_wih_kernel<<<4096, 256>>>(W_ih);                                 // 0
    conv_whh_kernel<<<256, 256>>>(W_hh);                                  // 1
    gat_kernel<<<GM, 256, SMEM_GAT>>>(x, adj, W, a_src, a_dst, gat_b);    // 2

    dim3 gg(GN / BN, GM / BM);
    tc_gemm_kernel<<<gg, 256, SMEM_DYN>>>(b_ih, b_hh);                    // 3 (profiled)

    lstm_kernel<<<dim3(LCL, Bz), 1024, LSTM_SMEM_DYN>>>();                // 4
    out_kernel<<<Bz, 256>>>(Wo, bo, out);                                 // 5
}

// round 14
// speedup vs baseline: 1.2102x; 1.0915x over previous
#include <cuda_runtime.h>
#include <cuda_bf16.h>
#include <cuda_fp16.h>
#include <math.h>
#include <stdint.h>

// Problem dims
#define Bz   32
#define Tz   32
#define Nz   256
#define FIN  32
#define FOUT 32
#define Hz   256
#define INz  8192
#define G4   1024
#define GM   1024
#define GK   8192
#define GN   1024

// GEMM tiling (fp16 1-pass)
#define BM 128
#define BN 64
#define BK 64
#define NIT (GK / BK)
#define NSTAGE 5
#define OFF_BH 16384
#define STAGE_B 24576
#define SMEM_DYN (NSTAGE * STAGE_B)   // 120 KB

// GAT smem layout (dynamic) — conflict-free padded strides
#define HSTR 80
#define ASTR 48
#define GAT_SH_HI   0
#define GAT_SH_LO   20480
#define GAT_AL_HI   40960
#define GAT_AL_LO   65536
#define ABUF        12288
#define GAT_SSRC    90112
#define GAT_SL      91136
#define GAT_SW      92160
#define GAT_SAS     96256
#define GAT_SAD     96384
#define GAT_SBIAS   96512
#define SMEM_GAT    96640

// LSTM cluster config
#define LCL 4
#define LSTM_WSM_F4 (12 * 1024)
#define LSTM_SMEM_DYN (LSTM_WSM_F4 * 16)   // 192 KB

// ---------------------------------------------------------------------------
// seq/wih: plain fp16, swizzled tiled layout:
// offset = ((rowtile*128 + kchunk) << 14) + row*128 + ((seg^(row&7))<<4) + (k&7)*2
// ---------------------------------------------------------------------------
__device__ __align__(128) __half g_seq[(size_t)GM * GK];
__device__ __align__(128) __half g_wih[(size_t)GN * GK];
__device__ float g_gates[(size_t)GM * G4];
__device__ float4 g_whhT[(Hz / 4) * G4];
__device__ float g_hlast[Bz * Hz];

// ---------------------------------------------------------------------------
__device__ __forceinline__ uint32_t smem_u32(const void* p) {
    return (uint32_t)__cvta_generic_to_shared(p);
}

#define MBARRIER_INIT(addr, cnt) \
    asm volatile("mbarrier.init.shared.b64 [%0], %1;" :: "r"(addr), "r"(cnt) : "memory")
#define MBARRIER_EXPECT_TX(addr, bytes) \
    asm volatile("mbarrier.arrive.expect_tx.shared.b64 _, [%0], %1;" :: "r"(addr), "r"(bytes) : "memory")
#define MBARRIER_WAIT_PARITY(addr, par) do {                                        \
    uint32_t _mbar = (addr); uint32_t _p = (par); uint32_t _done;                   \
    asm volatile("{\n\t.reg .pred p;\n\t"                                           \
        "mbarrier.try_wait.parity.acquire.cta.shared::cta.b64 p, [%1], %2;\n\t"     \
        "selp.b32 %0, 1, 0, p;\n\t}"                                                \
        : "=r"(_done) : "r"(_mbar), "r"(_p) : "memory");                            \
    if (!_done) {                                                                   \
        asm volatile("{\n\t.reg .pred P1;\n\t"                                      \
            "WAIT_LOOP_%=:\n\t"                                                     \
            "mbarrier.try_wait.parity.acquire.cta.shared::cta.b64 P1, [%0], %1, 0x989680;\n\t" \
            "@P1 bra.uni WAIT_DONE_%=;\n\t"                                         \
            "bra.uni WAIT_LOOP_%=;\n\t"                                             \
            "WAIT_DONE_%=:\n\t}"                                                    \
            :: "r"(_mbar), "r"(_p) : "memory");                                     \
    } } while (0)

#define BULK_G2S(dst, src, bytes, mbar) \
    asm volatile("cp.async.bulk.shared::cluster.global.mbarrier::complete_tx::bytes [%0], [%1], %2, [%3];" \
        :: "r"(dst), "l"(src), "r"(bytes), "r"(mbar) : "memory")

#define FENCE_ASYNC() asm volatile("fence.proxy.async.shared::cta;" ::: "memory")

#define CLUSTER_SYNC() do { \
    asm volatile("barrier.cluster.arrive.aligned;" ::: "memory"); \
    asm volatile("barrier.cluster.wait.aligned;" ::: "memory"); \
} while (0)

#define LDSM_X4(r0, r1, r2, r3, addr) \
    asm volatile("ldmatrix.sync.aligned.m8n8.x4.shared.b16 {%0,%1,%2,%3}, [%4];" \
        : "=r"(r0), "=r"(r1), "=r"(r2), "=r"(r3) : "r"(addr))
#define LDSM_X4T(r0, r1, r2, r3, addr) \
    asm volatile("ldmatrix.sync.aligned.m8n8.x4.trans.shared.b16 {%0,%1,%2,%3}, [%4];" \
        : "=r"(r0), "=r"(r1), "=r"(r2), "=r"(r3) : "r"(addr))

// bf16 mma (GAT path)
__device__ __forceinline__ void mma16816(float* d, const uint32_t* a, const uint32_t* b) {
    asm volatile(
        "mma.sync.aligned.m16n8k16.row.col.f32.bf16.bf16.f32 "
        "{%0,%1,%2,%3}, {%4,%5,%6,%7}, {%8,%9}, {%0,%1,%2,%3};"
        : "+f"(d[0]), "+f"(d[1]), "+f"(d[2]), "+f"(d[3])
        : "r"(a[0]), "r"(a[1]), "r"(a[2]), "r"(a[3]), "r"(b[0]), "r"(b[1]));
}
// fp16 mma (big GEMM path)
__device__ __forceinline__ void mma16816h(float* d, const uint32_t* a, const uint32_t* b) {
    asm volatile(
        "mma.sync.aligned.m16n8k16.row.col.f32.f16.f16.f32 "
        "{%0,%1,%2,%3}, {%4,%5,%6,%7}, {%8,%9}, {%0,%1,%2,%3};"
        : "+f"(d[0]), "+f"(d[1]), "+f"(d[2]), "+f"(d[3])
        : "r"(a[0]), "r"(a[1]), "r"(a[2]), "r"(a[3]), "r"(b[0]), "r"(b[1]));
}

__device__ __forceinline__ uint32_t pack_bf16x2(float v0, float v1) {
    unsigned short a = __bfloat16_as_ushort(__float2bfloat16(v0));
    unsigned short b = __bfloat16_as_ushort(__float2bfloat16(v1));
    return ((uint32_t)b << 16) | a;
}
__device__ __forceinline__ void split_bf16(float v, float& hi, float& lo) {
    __nv_bfloat16 h = __float2bfloat16(v);
    hi = __bfloat162float(h);
    lo = v - hi;
}
__device__ __forceinline__ uint32_t pack_f16x2(float v0, float v1) {
    __half2 h = __floats2half2_rn(v0, v1);
    return *(uint32_t*)&h;
}

// ---------------------------------------------------------------------------
// Kernel 1: GAT per (b,t). Tensor-core alpha@h (bf16 3-pass), padded smem.
// Epilogue writes seq as plain fp16 into swizzled tiled layout.
// ---------------------------------------------------------------------------
__global__ __launch_bounds__(256) void gat_kernel(
    const float* __restrict__ x, const float* __restrict__ adj,
    const float* __restrict__ W, const float* __restrict__ a_src,
    const float* __restrict__ a_dst, const float* __restrict__ gat_b)
{
    extern __shared__ __align__(128) unsigned char gsm[];
    const uint32_t smb = smem_u32(gsm);
    float* ssrc_f  = (float*)(gsm + GAT_SSRC);
    float* sl_f    = (float*)(gsm + GAT_SL);
    float* sW_f    = (float*)(gsm + GAT_SW);
    float* sas_f   = (float*)(gsm + GAT_SAS);
    float* sad_f   = (float*)(gsm + GAT_SAD);
    float* sbias_f = (float*)(gsm + GAT_SBIAS);

    const int bt  = blockIdx.x;
    const int tid = threadIdx.x;
    const int lane = tid & 31;
    const int wid  = tid >> 5;
    const float* xb   = x   + (size_t)bt * Nz * FIN;
    const float* adjb = adj + (size_t)bt * Nz * Nz;

    for (int i = tid; i < FIN * FOUT; i += 256) sW_f[i] = W[i];
    if (tid < FOUT) { sas_f[tid] = a_src[tid]; sad_f[tid] = a_dst[tid]; sbias_f[tid] = gat_b[tid]; }
    __syncthreads();

    float xv[FIN];
#pragma unroll
    for (int k = 0; k < FIN; k++) xv[k] = xb[tid * FIN + k];
    float hv[FOUT];
    float vsrc = 0.f, vdst = 0.f;
#pragma unroll
    for (int o = 0; o < FOUT; o++) {
        float acc = 0.f;
#pragma unroll
        for (int k = 0; k < FIN; k++) acc = fmaf(xv[k], sW_f[k * FOUT + o], acc);
        hv[o] = acc;
        vsrc = fmaf(acc, sas_f[o], vsrc);
        vdst = fmaf(acc, sad_f[o], vdst);
    }
    ssrc_f[tid] = vsrc;
#pragma unroll
    for (int g = 0; g < 4; g++) {
        float h8h[8], h8l[8];
#pragma unroll
        for (int e = 0; e < 8; e++) split_bf16(hv[g*8 + e], h8h[e], h8l[e]);
        uint4 uh = { pack_bf16x2(h8h[0],h8h[1]), pack_bf16x2(h8h[2],h8h[3]),
                     pack_bf16x2(h8h[4],h8h[5]), pack_bf16x2(h8h[6],h8h[7]) };
        uint4 ul = { pack_bf16x2(h8l[0],h8l[1]), pack_bf16x2(h8l[2],h8l[3]),
                     pack_bf16x2(h8l[4],h8l[5]), pack_bf16x2(h8l[6],h8l[7]) };
        *(uint4*)(gsm + GAT_SH_HI + tid * HSTR + g * 16) = uh;
        *(uint4*)(gsm + GAT_SH_LO + tid * HSTR + g * 16) = ul;
    }
    __syncthreads();

    float d[2][4][4];
#pragma unroll
    for (int i = 0; i < 2; i++)
#pragma unroll
        for (int j = 0; j < 4; j++)
#pragma unroll
            for (int q = 0; q < 4; q++) d[i][j][q] = 0.f;
    float l = 0.f;

    const int i0 = wid * 32;
    const uint32_t lrow = (lane & 7) + ((lane >> 3) & 1) * 8;
    const uint32_t lhalf = (lane >> 4) & 1;
    const uint32_t aAddrBase = smb + GAT_AL_HI + (i0 + lrow) * ASTR + lhalf * 16;
    const uint32_t bAddrBase = smb + GAT_SH_HI + lrow * HSTR + lhalf * 16;

    for (int c = 0; c < 16; c++) {
        const int buf = c & 1;
        float av[16];
#pragma unroll
        for (int jj = 0; jj < 16; jj++)
            av[jj] = adjb[(size_t)(c * 16 + jj) * Nz + tid];
        uint32_t phi[8], plo[8];
#pragma unroll
        for (int q = 0; q < 8; q++) {
            float p2[2];
#pragma unroll
            for (int u = 0; u < 2; u++) {
                int jj = q * 2 + u;
                int j  = c * 16 + jj;
                float e = vdst + ssrc_f[j];
                e = (e > 0.f) ? e : 0.2f * e;
                float pe = __expf(e);
                bool edge = (av[jj] != 0.f) | (j == tid);
                p2[u] = edge ? pe : 0.f;
                l += p2[u];
            }
            float h0, l0, h1, l1;
            split_bf16(p2[0], h0, l0);
            split_bf16(p2[1], h1, l1);
            phi[q] = pack_bf16x2(h0, h1);
            plo[q] = pack_bf16x2(l0, l1);
        }
        {
            unsigned char* arow = gsm + buf * ABUF + tid * ASTR;
            *(uint4*)(arow + GAT_AL_HI)      = *(uint4*)&phi[0];
            *(uint4*)(arow + GAT_AL_HI + 16) = *(uint4*)&phi[4];
            *(uint4*)(arow + GAT_AL_LO)      = *(uint4*)&plo[0];
            *(uint4*)(arow + GAT_AL_LO + 16) = *(uint4*)&plo[4];
        }
        __syncthreads();

        uint32_t ah[2][4], al[2][4], bh[2][4], bl[2][4];
        uint32_t aA = aAddrBase + buf * ABUF;
        LDSM_X4(ah[0][0], ah[0][1], ah[0][2], ah[0][3], aA);
        LDSM_X4(ah[1][0], ah[1][1], ah[1][2], ah[1][3], aA + 16 * ASTR);
        LDSM_X4(al[0][0], al[0][1], al[0][2], al[0][3], aA + (GAT_AL_LO - GAT_AL_HI));
        LDSM_X4(al[1][0], al[1][1], al[1][2], al[1][3], aA + (GAT_AL_LO - GAT_AL_HI) + 16 * ASTR);
        uint32_t bA = bAddrBase + c * 16 * HSTR;
        LDSM_X4T(bh[0][0], bh[0][1], bh[0][2], bh[0][3], bA);
        LDSM_X4T(bh[1][0], bh[1][1], bh[1][2], bh[1][3], bA + 32);
        LDSM_X4T(bl[0][0], bl[0][1], bl[0][2], bl[0][3], bA + (GAT_SH_LO - GAT_SH_HI));
        LDSM_X4T(bl[1][0], bl[1][1], bl[1][2], bl[1][3], bA + (GAT_SH_LO - GAT_SH_HI) + 32);
#pragma unroll
        for (int mt = 0; mt < 2; mt++)
#pragma unroll
            for (int ng = 0; ng < 2; ng++)
#pragma unroll
                for (int hf = 0; hf < 2; hf++) {
                    float* dd = d[mt][ng * 2 + hf];
                    mma16816(dd, ah[mt], &bh[ng][hf * 2]);
                    mma16816(dd, ah[mt], &bl[ng][hf * 2]);
                    mma16816(dd, al[mt], &bh[ng][hf * 2]);
                }
    }

    sl_f[tid] = 1.f / l;
    __syncthreads();

    const int mtile = bt >> 7, mrow = bt & 127;
    unsigned char* seqp = (unsigned char*)g_seq + (((size_t)mtile * 128) << 14);
#pragma unroll
    for (int mt = 0; mt < 2; mt++) {
        int r0 = i0 + mt * 16 + (lane >> 2);
        int r1 = r0 + 8;
        float inv0 = sl_f[r0], inv1 = sl_f[r1];
#pragma unroll
        for (int nt = 0; nt < 4; nt++) {
            int o = nt * 8 + (lane & 3) * 2;
            float b0 = sbias_f[o], b1 = sbias_f[o + 1];
            float v00 = fmaf(d[mt][nt][0], inv0, b0);
            float v01 = fmaf(d[mt][nt][1], inv0, b1);
            float v10 = fmaf(d[mt][nt][2], inv1, b0);
            float v11 = fmaf(d[mt][nt][3], inv1, b1);
            {
                int k0 = r0 * 32 + o;
                uint32_t byte = (uint32_t)mrow * 128 + (k0 & 63) * 2;
                uint32_t sw = byte ^ ((byte >> 3) & 0x70);
                size_t off = ((size_t)(k0 >> 6) << 14) + sw;
                *(uint32_t*)(seqp + off) = pack_f16x2(v00, v01);
            }
            {
                int k1 = r1 * 32 + o;
                uint32_t byte = (uint32_t)mrow * 128 + (k1 & 63) * 2;
                uint32_t sw = byte ^ ((byte >> 3) & 0x70);
                size_t off = ((size_t)(k1 >> 6) << 14) + sw;
                *(uint32_t*)(seqp + off) = pack_f16x2(v10, v11);
            }
        }
    }
}

// ---------------------------------------------------------------------------
// Kernel 1b: W_ih fp32 -> swizzled tiled fp16 (single copy; 4096 blocks)
// ---------------------------------------------------------------------------
__global__ __launch_bounds__(256) void conv_wih_kernel(const float* __restrict__ W_ih)
{
    size_t t = (size_t)blockIdx.x * 256 + threadIdx.x;
    int n = (int)(t >> 10);
    int s = (int)(t & 1023);
    int k0 = s * 8;
    const float* src = W_ih + (size_t)n * GK + k0;
    float4 v0 = *(const float4*)(src);
    float4 v1 = *(const float4*)(src + 4);
    int ntile = n >> 7, nrow = n & 127, chunk = s >> 3, seg = s & 7;
    size_t off = (((size_t)(ntile * 128 + chunk)) << 14) + nrow * 128
               + (uint32_t)((seg ^ (nrow & 7)) << 4);
    uint4 u;
    u.x = pack_f16x2(v0.x, v0.y); u.y = pack_f16x2(v0.z, v0.w);
    u.z = pack_f16x2(v1.x, v1.y); u.w = pack_f16x2(v1.z, v1.w);
    *(uint4*)((unsigned char*)g_wih + off) = u;
}

// ---------------------------------------------------------------------------
// Kernel 1c: W_hh -> packed transpose (256 blocks)
// ---------------------------------------------------------------------------
__global__ __launch_bounds__(256) void conv_whh_kernel(const float* __restrict__ W_hh)
{
    int t = blockIdx.x * 256 + threadIdx.x;
    int g  = t & 1023;
    int k4 = t >> 10;
    float4 v = *(const float4*)(W_hh + (size_t)g * Hz + k4 * 4);
    g_whhT[k4 * G4 + g] = v;
}

// ---------------------------------------------------------------------------
// Kernel 2: fp16 1-pass GEMM: D = A·B. 256 threads, 5 stages.
// ---------------------------------------------------------------------------
__global__ __launch_bounds__(256) void tc_gemm_kernel(
    const float* __restrict__ b_ih, const float* __restrict__ b_hh)
{
    extern __shared__ __align__(128) unsigned char dsmem[];
    __shared__ __align__(8) unsigned long long s_full[NSTAGE];
    const uint32_t dsm = smem_u32(dsmem);

    const int tid  = threadIdx.x;
    const int lane = tid & 31;
    const int wid  = tid >> 5;
    const int warp_m = wid >> 1;
    const int warp_n = wid & 1;
    const int mblk = blockIdx.y * BM;
    const int nblk = blockIdx.x * BN;
    const int mtile = blockIdx.y;
    const int ntile = blockIdx.x >> 1;
    const size_t bhalf = (size_t)(blockIdx.x & 1) * 8192;

    if (tid == 0) {
        for (int p = 0; p < NSTAGE; p++) MBARRIER_INIT(smem_u32(&s_full[p]), 1);
        FENCE_ASYNC();
    }
    __syncthreads();

    const unsigned char* srcA = (const unsigned char*)g_seq + (((size_t)mtile * 128) << 14);
    const unsigned char* srcB = (const unsigned char*)g_wih + (((size_t)ntile * 128) << 14) + bhalf;

    auto issue_stage = [&](int st, int it) {
        uint32_t sb = dsm + st * STAGE_B;
        uint32_t fb = smem_u32(&s_full[st]);
        size_t off = (size_t)it << 14;
        MBARRIER_EXPECT_TX(fb, STAGE_B);
        BULK_G2S(sb,          srcA + off, 16384, fb);
        BULK_G2S(sb + OFF_BH, srcB + off,  8192, fb);
    };

    if (tid == 0) {
#pragma unroll
        for (int p = 0; p < NSTAGE; p++) issue_stage(p, p);
    }

    const int rA  = warp_m * 32 + (lane & 7) + ((lane >> 3) & 1) * 8;
    const int aHf = lane >> 4;
    const int r7a = rA & 7;
    const int rB  = warp_n * 32 + (lane & 7) + ((lane >> 4) & 1) * 8;
    const int bHf = (lane >> 3) & 1;
    const int r7b = rB & 7;
    const uint32_t aoff0 = (uint32_t)rA * 128;
    const uint32_t aoff1 = aoff0 + 16 * 128;
    const uint32_t boff0 = (uint32_t)rB * 128;
    const uint32_t boff1 = boff0 + 16 * 128;

    float d[2][4][4];
#pragma unroll
    for (int i = 0; i < 2; i++)
#pragma unroll
        for (int j = 0; j < 4; j++)
#pragma unroll
            for (int q = 0; q < 4; q++) d[i][j][q] = 0.f;

    for (int it = 0; it < NIT; it++) {
        int s = it % NSTAGE;
        MBARRIER_WAIT_PARITY(smem_u32(&s_full[s]), (it / NSTAGE) & 1);

        uint32_t sA = dsm + s * STAGE_B;
        uint32_t sB = sA + OFF_BH;
#pragma unroll
        for (int ks = 0; ks < 4; ks++) {
            int kseg = ks * 2;
            uint32_t a[2][4], b[2][4];
            {
                uint32_t asg = (uint32_t)(((kseg + aHf) ^ r7a) << 4);
                uint32_t ad0 = sA + aoff0 + asg;
                uint32_t ad1 = sA + aoff1 + asg;
                LDSM_X4(a[0][0], a[0][1], a[0][2], a[0][3], ad0);
                LDSM_X4(a[1][0], a[1][1], a[1][2], a[1][3], ad1);
            }
            {
                uint32_t bsg = (uint32_t)(((kseg + bHf) ^ r7b) << 4);
                uint32_t bd0 = sB + boff0 + bsg;
                uint32_t bd1 = sB + boff1 + bsg;
                LDSM_X4(b[0][0], b[0][1], b[0][2], b[0][3], bd0);
                LDSM_X4(b[1][0], b[1][1], b[1][2], b[1][3], bd1);
            }
#pragma unroll
            for (int mt = 0; mt < 2; mt++)
#pragma unroll
                for (int p = 0; p < 2; p++)
#pragma unroll
                    for (int hf = 0; hf < 2; hf++)
                        mma16816h(d[mt][p * 2 + hf], a[mt], &b[p][hf * 2]);
        }
        __syncthreads();
        if (tid == 0 && it + NSTAGE < NIT) issue_stage(s, it + NSTAGE);
    }

#pragma unroll
    for (int mt = 0; mt < 2; mt++) {
#pragma unroll
        for (int nt = 0; nt < 4; nt++) {
            int rowm = mblk + warp_m * 32 + mt * 16 + (lane >> 2);
            int coln = nblk + warp_n * 32 + nt * 8 + (lane & 3) * 2;
            float bi0 = b_ih[coln]     + b_hh[coln];
            float bi1 = b_ih[coln + 1] + b_hh[coln + 1];
            float* p0 = g_gates + (size_t)rowm * GN + coln;
            float* p1 = g_gates + (size_t)(rowm + 8) * GN + coln;
            float2 v0 = {d[mt][nt][0] + bi0, d[mt][nt][1] + bi1};
            float2 v1 = {d[mt][nt][2] + bi0, d[mt][nt][3] + bi1};
            *(float2*)p0 = v0;
            *(float2*)p1 = v1;
        }
    }
}

// ---------------------------------------------------------------------------
// Kernel 3: LSTM recurrence — cluster-4 k-split (unchanged)
// ---------------------------------------------------------------------------
__global__ __launch_bounds__(1024, 1) __cluster_dims__(LCL, 1, 1)
void lstm_kernel()
{
    extern __shared__ __align__(16) float4 wsm[];
    __shared__ __align__(16) float hloc[64];
    __shared__ __align__(16) float pbuf[2][LCL * 256];

    const int tid = threadIdx.x;
    uint32_t rank;
    asm("mov.u32 %0, %%cluster_ctarank;" : "=r"(rank));
    const int b = blockIdx.y;
    const int j = tid & 255;
    const int q = tid >> 8;
    const int ro = j >> 6;
    const int slot = (int)rank * 256 + q * 64 + (j & 63);

    uint32_t rem[2];
    {
        uint32_t l0 = smem_u32(&pbuf[0][slot]);
        uint32_t l1 = smem_u32(&pbuf[1][slot]);
        asm("mapa.shared::cluster.u32 %0, %1, %2;" : "=r"(rem[0]) : "r"(l0), "r"(ro));
        asm("mapa.shared::cluster.u32 %0, %1, %2;" : "=r"(rem[1]) : "r"(l1), "r"(ro));
    }

    const float4* wp = g_whhT + (size_t)(rank * 16) * G4 + tid;
#pragma unroll
    for (int i = 0; i < 12; i++) wsm[i * 1024 + tid] = wp[i * G4];

    if (tid < 64) hloc[tid] = 0.f;
    float c = 0.f;
    const float* pre = g_gates + (size_t)b * Tz * G4;
    const int hglob = rank * 64 + tid;

    __syncthreads();

    for (int t = 0; t < Tz; t++) {
        float a0 = 0.f, a1 = 0.f;
        const float4* h4 = (const float4*)hloc;
#pragma unroll
        for (int i = 0; i < 12; i += 2) {
            float4 w0 = wsm[i * 1024 + tid];
            float4 w1 = wsm[(i + 1) * 1024 + tid];
            float4 h0 = h4[i], h1 = h4[i + 1];
            a0 = fmaf(w0.x, h0.x, a0); a0 = fmaf(w0.y, h0.y, a0);
            a0 = fmaf(w0.z, h0.z, a0); a0 = fmaf(w0.w, h0.w, a0);
            a1 = fmaf(w1.x, h1.x, a1); a1 = fmaf(w1.y, h1.y, a1);
            a1 = fmaf(w1.z, h1.z, a1); a1 = fmaf(w1.w, h1.w, a1);
        }
#pragma unroll
        for (int i = 12; i < 16; i += 2) {
            float4 w0 = wp[i * G4];
            float4 w1 = wp[(i + 1) * G4];
            float4 h0 = h4[i], h1 = h4[i + 1];
            a0 = fmaf(w0.x, h0.x, a0); a0 = fmaf(w0.y, h0.y, a0);
            a0 = fmaf(w0.z, h0.z, a0); a0 = fmaf(w0.w, h0.w, a0);
            a1 = fmaf(w1.x, h1.x, a1); a1 = fmaf(w1.y, h1.y, a1);
            a1 = fmaf(w1.z, h1.z, a1); a1 = fmaf(w1.w, h1.w, a1);
        }
        float partial = a0 + a1;

        asm volatile("st.shared::cluster.b32 [%0], %1;"
                     :: "r"(rem[t & 1]), "r"(__float_as_uint(partial)) : "memory");
        CLUSTER_SYNC();

        if (tid < 64) {
            const float* pb = pbuf[t & 1];
            float gs[4];
#pragma unroll
            for (int qq = 0; qq < 4; qq++) {
                float s = pre[t * G4 + qq * 256 + hglob];
#pragma unroll
                for (int src = 0; src < LCL; src++)
                    s += pb[src * 256 + qq * 64 + tid];
                gs[qq] = s;
            }
            float gi = 1.f / (1.f + __expf(-gs[0]));
            float gf = 1.f / (1.f + __expf(-gs[1]));
            float gg = tanhf(gs[2]);
            float go = 1.f / (1.f + __expf(-gs[3]));
            c = gf * c + gi * gg;
            hloc[tid] = go * tanhf(c);
        }
        __syncthreads();
    }

    if (tid < 64) g_hlast[b * Hz + hglob] = hloc[tid];
    CLUSTER_SYNC();
}

// ---------------------------------------------------------------------------
// Kernel 4: output linear
// ---------------------------------------------------------------------------
__global__ __launch_bounds__(256) void out_kernel(
    const float* __restrict__ Wo, const float* __restrict__ bo,
    float* __restrict__ out)
{
    const int b = blockIdx.x, n = threadIdx.x;
    const float4* h4 = (const float4*)(g_hlast + b * Hz);
    const float4* w4 = (const float4*)(Wo + n * Hz);
    float acc = bo[n];
#pragma unroll 8
    for (int k = 0; k < Hz / 4; k++) {
        float4 w = w4[k], h = h4[k];
        acc = fmaf(w.x, h.x, acc);
        acc = fmaf(w.y, h.y, acc);
        acc = fmaf(w.z, h.z, acc);
        acc = fmaf(w.w, h.w, acc);
    }
    out[b * Nz + n] = acc;
}

// ---------------------------------------------------------------------------
extern "C" void kernel_launch(void* const* d_in, const int* in_sizes, int n_in,
                              void* d_out, int out_size)
{
    const float* x     = (const float*)d_in[0];
    const float* adj   = (const float*)d_in[1];
    const float* W     = (const float*)d_in[2];
    const float* a_src = (const float*)d_in[3];
    const float* a_dst = (const float*)d_in[4];
    const float* gat_b = (const float*)d_in[5];
    const float* W_ih  = (const float*)d_in[6];
    const float* W_hh  = (const float*)d_in[7];
    const float* b_ih  = (const float*)d_in[8];
    const float* b_hh  = (const float*)d_in[9];
    const float* Wo    = (const float*)d_in[10];
    const float* bo    = (const float*)d_in[11];
    float* out = (float*)d_out;

    cudaFuncSetAttribute(tc_gemm_kernel,
                         cudaFuncAttributeMaxDynamicSharedMemorySize, SMEM_DYN);
    cudaFuncSetAttribute(gat_kernel,
                         cudaFuncAttributeMaxDynamicSharedMemorySize, SMEM_GAT);
    cudaFuncSetAttribute(lstm_kernel,
                         cudaFuncAttributeMaxDynamicSharedMemorySize, LSTM_SMEM_DYN);

    // index 3 (0-based) = ncu profiled slot -> tc_gemm
    conv_wih_kernel<<<4096, 256>>>(W_ih);                                 // 0
    conv_whh_kernel<<<256, 256>>>(W_hh);                                  // 1
    gat_kernel<<<GM, 256, SMEM_GAT>>>(x, adj, W, a_src, a_dst, gat_b);    // 2

    dim3 gg(GN / BN, GM / BM);
    tc_gemm_kernel<<<gg, 256, SMEM_DYN>>>(b_ih, b_hh);                    // 3 (profiled)

    lstm_kernel<<<dim3(LCL, Bz), 1024, LSTM_SMEM_DYN>>>();                // 4
    out_kernel<<<Bz, 256>>>(Wo, bo, out);                                 // 5
}

// round 15
// speedup vs baseline: 1.4370x; 1.1873x over previous
#include <cuda_runtime.h>
#include <cuda_bf16.h>
#include <cuda_fp16.h>
#include <math.h>
#include <stdint.h>

// Problem dims
#define Bz   32
#define Tz   32
#define Nz   256
#define FIN  32
#define FOUT 32
#define Hz   256
#define INz  8192
#define G4   1024
#define GM   1024
#define GK   8192
#define GN   1024

// GEMM tiling (fp16 1-pass)
#define BM 128
#define BN 64
#define BK 64
#define NIT (GK / BK)
#define NSTAGE 5
#define OFF_BH 16384
#define STAGE_B 24576
#define SMEM_DYN (NSTAGE * STAGE_B)   // 120 KB

// GAT smem layout (fp16 1-pass) — conflict-free padded strides
#define HSTR 80
#define ASTR 48
#define GAT_SH     0          // h fp16 [256] rows, 80B stride (64B used)
#define GAT_AL     20480      // alpha fp16 [2 bufs][256] rows, 48B stride (32B used)
#define ABUF       12288
#define GAT_SSRC   45056
#define GAT_SL     46080
#define GAT_SW     47104
#define GAT_SAS    51200
#define GAT_SAD    51328
#define GAT_SBIAS  51456
#define SMEM_GAT   51584

// LSTM cluster config
#define LCL 4
#define LSTM_WSM_F4 (12 * 1024)
#define LSTM_SMEM_DYN (LSTM_WSM_F4 * 16)   // 192 KB

// ---------------------------------------------------------------------------
__device__ __align__(128) __half g_seq[(size_t)GM * GK];
__device__ __align__(128) __half g_wih[(size_t)GN * GK];
__device__ float g_gates[(size_t)GM * G4];
__device__ float4 g_whhT[(Hz / 4) * G4];
__device__ float g_hlast[Bz * Hz];

// ---------------------------------------------------------------------------
__device__ __forceinline__ uint32_t smem_u32(const void* p) {
    return (uint32_t)__cvta_generic_to_shared(p);
}

#define MBARRIER_INIT(addr, cnt) \
    asm volatile("mbarrier.init.shared.b64 [%0], %1;" :: "r"(addr), "r"(cnt) : "memory")
#define MBARRIER_EXPECT_TX(addr, bytes) \
    asm volatile("mbarrier.arrive.expect_tx.shared.b64 _, [%0], %1;" :: "r"(addr), "r"(bytes) : "memory")
#define MBARRIER_WAIT_PARITY(addr, par) do {                                        \
    uint32_t _mbar = (addr); uint32_t _p = (par); uint32_t _done;                   \
    asm volatile("{\n\t.reg .pred p;\n\t"                                           \
        "mbarrier.try_wait.parity.acquire.cta.shared::cta.b64 p, [%1], %2;\n\t"     \
        "selp.b32 %0, 1, 0, p;\n\t}"                                                \
        : "=r"(_done) : "r"(_mbar), "r"(_p) : "memory");                            \
    if (!_done) {                                                                   \
        asm volatile("{\n\t.reg .pred P1;\n\t"                                      \
            "WAIT_LOOP_%=:\n\t"                                                     \
            "mbarrier.try_wait.parity.acquire.cta.shared::cta.b64 P1, [%0], %1, 0x989680;\n\t" \
            "@P1 bra.uni WAIT_DONE_%=;\n\t"                                         \
            "bra.uni WAIT_LOOP_%=;\n\t"                                             \
            "WAIT_DONE_%=:\n\t}"                                                    \
            :: "r"(_mbar), "r"(_p) : "memory");                                     \
    } } while (0)

#define BULK_G2S(dst, src, bytes, mbar) \
    asm volatile("cp.async.bulk.shared::cluster.global.mbarrier::complete_tx::bytes [%0], [%1], %2, [%3];" \
        :: "r"(dst), "l"(src), "r"(bytes), "r"(mbar) : "memory")

#define FENCE_ASYNC() asm volatile("fence.proxy.async.shared::cta;" ::: "memory")

#define CLUSTER_SYNC() do { \
    asm volatile("barrier.cluster.arrive.aligned;" ::: "memory"); \
    asm volatile("barrier.cluster.wait.aligned;" ::: "memory"); \
} while (0)

#define LDSM_X4(r0, r1, r2, r3, addr) \
    asm volatile("ldmatrix.sync.aligned.m8n8.x4.shared.b16 {%0,%1,%2,%3}, [%4];" \
        : "=r"(r0), "=r"(r1), "=r"(r2), "=r"(r3) : "r"(addr))
#define LDSM_X4T(r0, r1, r2, r3, addr) \
    asm volatile("ldmatrix.sync.aligned.m8n8.x4.trans.shared.b16 {%0,%1,%2,%3}, [%4];" \
        : "=r"(r0), "=r"(r1), "=r"(r2), "=r"(r3) : "r"(addr))

// fp16 mma
__device__ __forceinline__ void mma16816h(float* d, const uint32_t* a, const uint32_t* b) {
    asm volatile(
        "mma.sync.aligned.m16n8k16.row.col.f32.f16.f16.f32 "
        "{%0,%1,%2,%3}, {%4,%5,%6,%7}, {%8,%9}, {%0,%1,%2,%3};"
        : "+f"(d[0]), "+f"(d[1]), "+f"(d[2]), "+f"(d[3])
        : "r"(a[0]), "r"(a[1]), "r"(a[2]), "r"(a[3]), "r"(b[0]), "r"(b[1]));
}

__device__ __forceinline__ uint32_t pack_f16x2(float v0, float v1) {
    __half2 h = __floats2half2_rn(v0, v1);
    return *(uint32_t*)&h;
}

// ---------------------------------------------------------------------------
// Kernel 1: GAT per (b,t). fp16 1-pass alpha@h on tensor cores.
// ---------------------------------------------------------------------------
__global__ __launch_bounds__(256) void gat_kernel(
    const float* __restrict__ x, const float* __restrict__ adj,
    const float* __restrict__ W, const float* __restrict__ a_src,
    const float* __restrict__ a_dst, const float* __restrict__ gat_b)
{
    extern __shared__ __align__(128) unsigned char gsm[];
    const uint32_t smb = smem_u32(gsm);
    float* ssrc_f  = (float*)(gsm + GAT_SSRC);
    float* sl_f    = (float*)(gsm + GAT_SL);
    float* sW_f    = (float*)(gsm + GAT_SW);
    float* sas_f   = (float*)(gsm + GAT_SAS);
    float* sad_f   = (float*)(gsm + GAT_SAD);
    float* sbias_f = (float*)(gsm + GAT_SBIAS);

    const int bt  = blockIdx.x;
    const int tid = threadIdx.x;
    const int lane = tid & 31;
    const int wid  = tid >> 5;
    const float* xb   = x   + (size_t)bt * Nz * FIN;
    const float* adjb = adj + (size_t)bt * Nz * Nz;

    for (int i = tid; i < FIN * FOUT; i += 256) sW_f[i] = W[i];
    if (tid < FOUT) { sas_f[tid] = a_src[tid]; sad_f[tid] = a_dst[tid]; sbias_f[tid] = gat_b[tid]; }
    __syncthreads();

    // ---- phase 1: h row for node tid (fp32 compute, fp16 store) ----
    float xv[FIN];
#pragma unroll
    for (int k = 0; k < FIN; k++) xv[k] = xb[tid * FIN + k];
    float hv[FOUT];
    float vsrc = 0.f, vdst = 0.f;
#pragma unroll
    for (int o = 0; o < FOUT; o++) {
        float acc = 0.f;
#pragma unroll
        for (int k = 0; k < FIN; k++) acc = fmaf(xv[k], sW_f[k * FOUT + o], acc);
        hv[o] = acc;
        vsrc = fmaf(acc, sas_f[o], vsrc);
        vdst = fmaf(acc, sad_f[o], vdst);
    }
    ssrc_f[tid] = vsrc;
#pragma unroll
    for (int g = 0; g < 4; g++) {
        uint4 u = { pack_f16x2(hv[g*8+0], hv[g*8+1]), pack_f16x2(hv[g*8+2], hv[g*8+3]),
                    pack_f16x2(hv[g*8+4], hv[g*8+5]), pack_f16x2(hv[g*8+6], hv[g*8+7]) };
        *(uint4*)(gsm + GAT_SH + tid * HSTR + g * 16) = u;
    }
    __syncthreads();

    // ---- phase 2: 16-source chunks; fp16 alpha -> smem; 1-pass MMA ----
    float d[2][4][4];
#pragma unroll
    for (int i = 0; i < 2; i++)
#pragma unroll
        for (int j = 0; j < 4; j++)
#pragma unroll
            for (int q = 0; q < 4; q++) d[i][j][q] = 0.f;
    float l = 0.f;

    const int i0 = wid * 32;
    const uint32_t lrow = (lane & 7) + ((lane >> 3) & 1) * 8;
    const uint32_t lhalf = (lane >> 4) & 1;
    const uint32_t aAddrBase = smb + GAT_AL + (i0 + lrow) * ASTR + lhalf * 16;
    const uint32_t bAddrBase = smb + GAT_SH + lrow * HSTR + lhalf * 16;

    for (int c = 0; c < 16; c++) {
        const int buf = c & 1;
        float av[16];
#pragma unroll
        for (int jj = 0; jj < 16; jj++)
            av[jj] = adjb[(size_t)(c * 16 + jj) * Nz + tid];
        uint32_t phi[8];
#pragma unroll
        for (int q = 0; q < 8; q++) {
            float p2[2];
#pragma unroll
            for (int u = 0; u < 2; u++) {
                int jj = q * 2 + u;
                int j  = c * 16 + jj;
                float e = vdst + ssrc_f[j];
                e = (e > 0.f) ? e : 0.2f * e;
                float pe = __expf(e);
                bool edge = (av[jj] != 0.f) | (j == tid);
                p2[u] = edge ? pe : 0.f;
                l += p2[u];
            }
            phi[q] = pack_f16x2(p2[0], p2[1]);
        }
        {
            unsigned char* arow = gsm + GAT_AL + buf * ABUF + tid * ASTR;
            *(uint4*)(arow)      = *(uint4*)&phi[0];
            *(uint4*)(arow + 16) = *(uint4*)&phi[4];
        }
        __syncthreads();

        uint32_t a[2][4], b[2][4];
        uint32_t aA = aAddrBase + buf * ABUF;
        LDSM_X4(a[0][0], a[0][1], a[0][2], a[0][3], aA);
        LDSM_X4(a[1][0], a[1][1], a[1][2], a[1][3], aA + 16 * ASTR);
        uint32_t bA = bAddrBase + c * 16 * HSTR;
        LDSM_X4T(b[0][0], b[0][1], b[0][2], b[0][3], bA);
        LDSM_X4T(b[1][0], b[1][1], b[1][2], b[1][3], bA + 32);
#pragma unroll
        for (int mt = 0; mt < 2; mt++)
#pragma unroll
            for (int ng = 0; ng < 2; ng++)
#pragma unroll
                for (int hf = 0; hf < 2; hf++)
                    mma16816h(d[mt][ng * 2 + hf], a[mt], &b[ng][hf * 2]);
    }

    sl_f[tid] = 1.f / l;
    __syncthreads();

    // ---- epilogue: scale, bias, write fp16 seq (swizzled tiled) ----
    const int mtile = bt >> 7, mrow = bt & 127;
    unsigned char* seqp = (unsigned char*)g_seq + (((size_t)mtile * 128) << 14);
#pragma unroll
    for (int mt = 0; mt < 2; mt++) {
        int r0 = i0 + mt * 16 + (lane >> 2);
        int r1 = r0 + 8;
        float inv0 = sl_f[r0], inv1 = sl_f[r1];
#pragma unroll
        for (int nt = 0; nt < 4; nt++) {
            int o = nt * 8 + (lane & 3) * 2;
            float b0 = sbias_f[o], b1 = sbias_f[o + 1];
            float v00 = fmaf(d[mt][nt][0], inv0, b0);
            float v01 = fmaf(d[mt][nt][1], inv0, b1);
            float v10 = fmaf(d[mt][nt][2], inv1, b0);
            float v11 = fmaf(d[mt][nt][3], inv1, b1);
            {
                int k0 = r0 * 32 + o;
                uint32_t byte = (uint32_t)mrow * 128 + (k0 & 63) * 2;
                uint32_t sw = byte ^ ((byte >> 3) & 0x70);
                size_t off = ((size_t)(k0 >> 6) << 14) + sw;
                *(uint32_t*)(seqp + off) = pack_f16x2(v00, v01);
            }
            {
                int k1 = r1 * 32 + o;
                uint32_t byte = (uint32_t)mrow * 128 + (k1 & 63) * 2;
                uint32_t sw = byte ^ ((byte >> 3) & 0x70);
                size_t off = ((size_t)(k1 >> 6) << 14) + sw;
                *(uint32_t*)(seqp + off) = pack_f16x2(v10, v11);
            }
        }
    }
}

// ---------------------------------------------------------------------------
// Kernel 1b: W_ih fp32 -> swizzled tiled fp16 (half rows per launch)
// ---------------------------------------------------------------------------
__global__ __launch_bounds__(256) void conv_wih_kernel(const float* __restrict__ W_ih, int n0)
{
    size_t t = (size_t)blockIdx.x * 256 + threadIdx.x;
    int n = n0 + (int)(t >> 10);
    int s = (int)(t & 1023);
    int k0 = s * 8;
    const float* src = W_ih + (size_t)n * GK + k0;
    float4 v0 = *(const float4*)(src);
    float4 v1 = *(const float4*)(src + 4);
    int ntile = n >> 7, nrow = n & 127, chunk = s >> 3, seg = s & 7;
    size_t off = (((size_t)(ntile * 128 + chunk)) << 14) + nrow * 128
               + (uint32_t)((seg ^ (nrow & 7)) << 4);
    uint4 u;
    u.x = pack_f16x2(v0.x, v0.y); u.y = pack_f16x2(v0.z, v0.w);
    u.z = pack_f16x2(v1.x, v1.y); u.w = pack_f16x2(v1.z, v1.w);
    *(uint4*)((unsigned char*)g_wih + off) = u;
}

// ---------------------------------------------------------------------------
// Kernel 1c: W_hh -> packed transpose (256 blocks)
// ---------------------------------------------------------------------------
__global__ __launch_bounds__(256) void conv_whh_kernel(const float* __restrict__ W_hh)
{
    int t = blockIdx.x * 256 + threadIdx.x;
    int g  = t & 1023;
    int k4 = t >> 10;
    float4 v = *(const float4*)(W_hh + (size_t)g * Hz + k4 * 4);
    g_whhT[k4 * G4 + g] = v;
}

// ---------------------------------------------------------------------------
// Kernel 2: fp16 1-pass GEMM: D = A·B. 256 threads, 5 stages.
// ---------------------------------------------------------------------------
__global__ __launch_bounds__(256) void tc_gemm_kernel(
    const float* __restrict__ b_ih, const float* __restrict__ b_hh)
{
    extern __shared__ __align__(128) unsigned char dsmem[];
    __shared__ __align__(8) unsigned long long s_full[NSTAGE];
    const uint32_t dsm = smem_u32(dsmem);

    const int tid  = threadIdx.x;
    const int lane = tid & 31;
    const int wid  = tid >> 5;
    const int warp_m = wid >> 1;
    const int warp_n = wid & 1;
    const int mblk = blockIdx.y * BM;
    const int nblk = blockIdx.x * BN;
    const int mtile = blockIdx.y;
    const int ntile = blockIdx.x >> 1;
    const size_t bhalf = (size_t)(blockIdx.x & 1) * 8192;

    if (tid == 0) {
        for (int p = 0; p < NSTAGE; p++) MBARRIER_INIT(smem_u32(&s_full[p]), 1);
        FENCE_ASYNC();
    }
    __syncthreads();

    const unsigned char* srcA = (const unsigned char*)g_seq + (((size_t)mtile * 128) << 14);
    const unsigned char* srcB = (const unsigned char*)g_wih + (((size_t)ntile * 128) << 14) + bhalf;

    auto issue_stage = [&](int st, int it) {
        uint32_t sb = dsm + st * STAGE_B;
        uint32_t fb = smem_u32(&s_full[st]);
        size_t off = (size_t)it << 14;
        MBARRIER_EXPECT_TX(fb, STAGE_B);
        BULK_G2S(sb,          srcA + off, 16384, fb);
        BULK_G2S(sb + OFF_BH, srcB + off,  8192, fb);
    };

    if (tid == 0) {
#pragma unroll
        for (int p = 0; p < NSTAGE; p++) issue_stage(p, p);
    }

    const int rA  = warp_m * 32 + (lane & 7) + ((lane >> 3) & 1) * 8;
    const int aHf = lane >> 4;
    const int r7a = rA & 7;
    const int rB  = warp_n * 32 + (lane & 7) + ((lane >> 4) & 1) * 8;
    const int bHf = (lane >> 3) & 1;
    const int r7b = rB & 7;
    const uint32_t aoff0 = (uint32_t)rA * 128;
    const uint32_t aoff1 = aoff0 + 16 * 128;
    const uint32_t boff0 = (uint32_t)rB * 128;
    const uint32_t boff1 = boff0 + 16 * 128;

    float d[2][4][4];
#pragma unroll
    for (int i = 0; i < 2; i++)
#pragma unroll
        for (int j = 0; j < 4; j++)
#pragma unroll
            for (int q = 0; q < 4; q++) d[i][j][q] = 0.f;

    for (int it = 0; it < NIT; it++) {
        int s = it % NSTAGE;
        MBARRIER_WAIT_PARITY(smem_u32(&s_full[s]), (it / NSTAGE) & 1);

        uint32_t sA = dsm + s * STAGE_B;
        uint32_t sB = sA + OFF_BH;
#pragma unroll
        for (int ks = 0; ks < 4; ks++) {
            int kseg = ks * 2;
            uint32_t a[2][4], b[2][4];
            {
                uint32_t asg = (uint32_t)(((kseg + aHf) ^ r7a) << 4);
                uint32_t ad0 = sA + aoff0 + asg;
                uint32_t ad1 = sA + aoff1 + asg;
                LDSM_X4(a[0][0], a[0][1], a[0][2], a[0][3], ad0);
                LDSM_X4(a[1][0], a[1][1], a[1][2], a[1][3], ad1);
            }
            {
                uint32_t bsg = (uint32_t)(((kseg + bHf) ^ r7b) << 4);
                uint32_t bd0 = sB + boff0 + bsg;
                uint32_t bd1 = sB + boff1 + bsg;
                LDSM_X4(b[0][0], b[0][1], b[0][2], b[0][3], bd0);
                LDSM_X4(b[1][0], b[1][1], b[1][2], b[1][3], bd1);
            }
#pragma unroll
            for (int mt = 0; mt < 2; mt++)
#pragma unroll
                for (int p = 0; p < 2; p++)
#pragma unroll
                    for (int hf = 0; hf < 2; hf++)
                        mma16816h(d[mt][p * 2 + hf], a[mt], &b[p][hf * 2]);
        }
        __syncthreads();
        if (tid == 0 && it + NSTAGE < NIT) issue_stage(s, it + NSTAGE);
    }

#pragma unroll
    for (int mt = 0; mt < 2; mt++) {
#pragma unroll
        for (int nt = 0; nt < 4; nt++) {
            int rowm = mblk + warp_m * 32 + mt * 16 + (lane >> 2);
            int coln = nblk + warp_n * 32 + nt * 8 + (lane & 3) * 2;
            float bi0 = b_ih[coln]     + b_hh[coln];
            float bi1 = b_ih[coln + 1] + b_hh[coln + 1];
            float* p0 = g_gates + (size_t)rowm * GN + coln;
            float* p1 = g_gates + (size_t)(rowm + 8) * GN + coln;
            float2 v0 = {d[mt][nt][0] + bi0, d[mt][nt][1] + bi1};
            float2 v1 = {d[mt][nt][2] + bi0, d[mt][nt][3] + bi1};
            *(float2*)p0 = v0;
            *(float2*)p1 = v1;
        }
    }
}

// ---------------------------------------------------------------------------
// Kernel 3: LSTM recurrence — cluster-4 k-split (unchanged)
// ---------------------------------------------------------------------------
__global__ __launch_bounds__(1024, 1) __cluster_dims__(LCL, 1, 1)
void lstm_kernel()
{
    extern __shared__ __align__(16) float4 wsm[];
    __shared__ __align__(16) float hloc[64];
    __shared__ __align__(16) float pbuf[2][LCL * 256];

    const int tid = threadIdx.x;
    uint32_t rank;
    asm("mov.u32 %0, %%cluster_ctarank;" : "=r"(rank));
    const int b = blockIdx.y;
    const int j = tid & 255;
    const int q = tid >> 8;
    const int ro = j >> 6;
    const int slot = (int)rank * 256 + q * 64 + (j & 63);

    uint32_t rem[2];
    {
        uint32_t l0 = smem_u32(&pbuf[0][slot]);
        uint32_t l1 = smem_u32(&pbuf[1][slot]);
        asm("mapa.shared::cluster.u32 %0, %1, %2;" : "=r"(rem[0]) : "r"(l0), "r"(ro));
        asm("mapa.shared::cluster.u32 %0, %1, %2;" : "=r"(rem[1]) : "r"(l1), "r"(ro));
    }

    const float4* wp = g_whhT + (size_t)(rank * 16) * G4 + tid;
#pragma unroll
    for (int i = 0; i < 12; i++) wsm[i * 1024 + tid] = wp[i * G4];

    if (tid < 64) hloc[tid] = 0.f;
    float c = 0.f;
    const float* pre = g_gates + (size_t)b * Tz * G4;
    const int hglob = rank * 64 + tid;

    __syncthreads();

    for (int t = 0; t < Tz; t++) {
        float a0 = 0.f, a1 = 0.f;
        const float4* h4 = (const float4*)hloc;
#pragma unroll
        for (int i = 0; i < 12; i += 2) {
            float4 w0 = wsm[i * 1024 + tid];
            float4 w1 = wsm[(i + 1) * 1024 + tid];
            float4 h0 = h4[i], h1 = h4[i + 1];
            a0 = fmaf(w0.x, h0.x, a0); a0 = fmaf(w0.y, h0.y, a0);
            a0 = fmaf(w0.z, h0.z, a0); a0 = fmaf(w0.w, h0.w, a0);
            a1 = fmaf(w1.x, h1.x, a1); a1 = fmaf(w1.y, h1.y, a1);
            a1 = fmaf(w1.z, h1.z, a1); a1 = fmaf(w1.w, h1.w, a1);
        }
#pragma unroll
        for (int i = 12; i < 16; i += 2) {
            float4 w0 = wp[i * G4];
            float4 w1 = wp[(i + 1) * G4];
            float4 h0 = h4[i], h1 = h4[i + 1];
            a0 = fmaf(w0.x, h0.x, a0); a0 = fmaf(w0.y, h0.y, a0);
            a0 = fmaf(w0.z, h0.z, a0); a0 = fmaf(w0.w, h0.w, a0);
            a1 = fmaf(w1.x, h1.x, a1); a1 = fmaf(w1.y, h1.y, a1);
            a1 = fmaf(w1.z, h1.z, a1); a1 = fmaf(w1.w, h1.w, a1);
        }
        float partial = a0 + a1;

        asm volatile("st.shared::cluster.b32 [%0], %1;"
                     :: "r"(rem[t & 1]), "r"(__float_as_uint(partial)) : "memory");
        CLUSTER_SYNC();

        if (tid < 64) {
            const float* pb = pbuf[t & 1];
            float gs[4];
#pragma unroll
            for (int qq = 0; qq < 4; qq++) {
                float s = pre[t * G4 + qq * 256 + hglob];
#pragma unroll
                for (int src = 0; src < LCL; src++)
                    s += pb[src * 256 + qq * 64 + tid];
                gs[qq] = s;
            }
            float gi = 1.f / (1.f + __expf(-gs[0]));
            float gf = 1.f / (1.f + __expf(-gs[1]));
            float gg = tanhf(gs[2]);
            float go = 1.f / (1.f + __expf(-gs[3]));
            c = gf * c + gi * gg;
            hloc[tid] = go * tanhf(c);
        }
        __syncthreads();
    }

    if (tid < 64) g_hlast[b * Hz + hglob] = hloc[tid];
    CLUSTER_SYNC();
}

// ---------------------------------------------------------------------------
// Kernel 4: output linear
// ---------------------------------------------------------------------------
__global__ __launch_bounds__(256) void out_kernel(
    const float* __restrict__ Wo, const float* __restrict__ bo,
    float* __restrict__ out)
{
    const int b = blockIdx.x, n = threadIdx.x;
    const float4* h4 = (const float4*)(g_hlast + b * Hz);
    const float4* w4 = (const float4*)(Wo + n * Hz);
    float acc = bo[n];
#pragma unroll 8
    for (int k = 0; k < Hz / 4; k++) {
        float4 w = w4[k], h = h4[k];
        acc = fmaf(w.x, h.x, acc);
        acc = fmaf(w.y, h.y, acc);
        acc = fmaf(w.z, h.z, acc);
        acc = fmaf(w.w, h.w, acc);
    }
    out[b * Nz + n] = acc;
}

// ---------------------------------------------------------------------------
extern "C" void kernel_launch(void* const* d_in, const int* in_sizes, int n_in,
                              void* d_out, int out_size)
{
    const float* x     = (const float*)d_in[0];
    const float* adj   = (const float*)d_in[1];
    const float* W     = (const float*)d_in[2];
    const float* a_src = (const float*)d_in[3];
    const float* a_dst = (const float*)d_in[4];
    const float* gat_b = (const float*)d_in[5];
    const float* W_ih  = (const float*)d_in[6];
    const float* W_hh  = (const float*)d_in[7];
    const float* b_ih  = (const float*)d_in[8];
    const float* b_hh  = (const float*)d_in[9];
    const float* Wo    = (const float*)d_in[10];
    const float* bo    = (const float*)d_in[11];
    float* out = (float*)d_out;

    cudaFuncSetAttribute(tc_gemm_kernel,
                         cudaFuncAttributeMaxDynamicSharedMemorySize, SMEM_DYN);
    cudaFuncSetAttribute(gat_kernel,
                         cudaFuncAttributeMaxDynamicSharedMemorySize, SMEM_GAT);
    cudaFuncSetAttribute(lstm_kernel,
                         cudaFuncAttributeMaxDynamicSharedMemorySize, LSTM_SMEM_DYN);

    // index 3 (0-based) = ncu profiled slot -> gat this round
    conv_wih_kernel<<<2048, 256>>>(W_ih, 0);                              // 0
    conv_wih_kernel<<<2048, 256>>>(W_ih, 512);                            // 1
    conv_whh_kernel<<<256, 256>>>(W_hh);                                  // 2
    gat_kernel<<<GM, 256, SMEM_GAT>>>(x, adj, W, a_src, a_dst, gat_b);    // 3 (profiled)

    dim3 gg(GN / BN, GM / BM);
    tc_gemm_kernel<<<gg, 256, SMEM_DYN>>>(b_ih, b_hh);                    // 4

    lstm_kernel<<<dim3(LCL, Bz), 1024, LSTM_SMEM_DYN>>>();                // 5
    out_kernel<<<Bz, 256>>>(Wo, bo, out);                                 // 6
}